// round 11
// baseline (speedup 1.0000x reference)
#include <cuda_runtime.h>
#include <cuda_bf16.h>
#include <math.h>
#include <stdint.h>

#define NQ    2048
#define NREF  100000
#define GENES 3467
#define DIM   512
#define TOPK  50
#define LN_EPS 1e-5f

#define KPAD1 3520          // GENES padded to mult of 32
#define NPAD  100352        // NREF padded to mult of 128
#define RS    40            // smem row stride in bf16 (80B, conflict-free ldmatrix)

// ---------------- scratch (device globals; no allocation allowed) ----------
__device__ __nv_bfloat16 g_w1t_hi[(size_t)DIM * KPAD1];
__device__ __nv_bfloat16 g_w1t_lo[(size_t)DIM * KPAD1];
__device__ __nv_bfloat16 g_w2t_hi[(size_t)DIM * DIM];
__device__ __nv_bfloat16 g_w2t_lo[(size_t)DIM * DIM];
__device__ __nv_bfloat16 g_g_hi[(size_t)NPAD * DIM];
__device__ __nv_bfloat16 g_g_lo[(size_t)NPAD * DIM];
__device__ __nv_bfloat16 g_embn[(size_t)NPAD * DIM];
__device__ __nv_bfloat16 g_qhi[(size_t)NQ * DIM];
__device__ float g_proj[(size_t)NPAD * DIM];
__device__ float g_emb [(size_t)NPAD * DIM];
__device__ float g_rnorm[NREF];
__device__ __nv_bfloat16 g_sim [(size_t)NQ * NPAD];   // bf16 ranking keys
__device__ int   g_idx [NQ * TOPK];

// ---------------- PTX helpers (base compute_103 features only) --------------
__device__ __forceinline__ uint32_t smem_u32(const void* p) {
    uint32_t a;
    asm("{ .reg .u64 t; cvta.to.shared.u64 t, %1; cvt.u32.u64 %0, t; }" : "=r"(a) : "l"(p));
    return a;
}
__device__ __forceinline__ void cp16(uint32_t sa, const void* ga) {
    asm volatile("cp.async.cg.shared.global [%0], [%1], 16;" :: "r"(sa), "l"(ga));
}
#define CP_COMMIT() asm volatile("cp.async.commit_group;" ::: "memory")
#define CP_WAIT(n)  asm volatile("cp.async.wait_group %0;" :: "n"(n) : "memory")

__device__ __forceinline__ void ldm_x4(uint32_t* r, uint32_t addr) {
    asm volatile("ldmatrix.sync.aligned.m8n8.x4.shared.b16 {%0,%1,%2,%3}, [%4];"
        : "=r"(r[0]), "=r"(r[1]), "=r"(r[2]), "=r"(r[3]) : "r"(addr));
}
__device__ __forceinline__ void mma16816(float* d, const uint32_t* a, const uint32_t* b) {
    asm volatile(
        "mma.sync.aligned.m16n8k16.row.col.f32.bf16.bf16.f32 "
        "{%0,%1,%2,%3}, {%4,%5,%6,%7}, {%8,%9}, {%0,%1,%2,%3};"
        : "+f"(d[0]), "+f"(d[1]), "+f"(d[2]), "+f"(d[3])
        : "r"(a[0]), "r"(a[1]), "r"(a[2]), "r"(a[3]), "r"(b[0]), "r"(b[1]));
}

// ---------------- bf16 split helpers ----------------------------------------
__device__ __forceinline__ void split2(float x, __nv_bfloat16& h, __nv_bfloat16& l) {
    h = __float2bfloat16(x);
    l = __float2bfloat16(x - __bfloat162float(h));
}
__device__ __forceinline__ float gelu_exact(float x) {
    return 0.5f * x * (1.0f + erff(x * 0.70710678118654752f));
}

#define TILE_B (128 * RS * 2)   // 10240 bytes per tile

// ---- shared compute core: one BK=32 block, 3-term or 1-term -----------------
template<int TERMS>
__device__ __forceinline__ void compute_block(
    float acc[4][4][4], uint32_t sbase, int wm, int wn, int lane)
{
    const uint32_t saHI = sbase;
    const uint32_t saLO = sbase + TILE_B;
    const uint32_t sbHI = sbase + ((TERMS == 3) ? 2 : 1) * TILE_B;
    const uint32_t sbLO = sbase + 3 * TILE_B;
    #pragma unroll
    for (int ks = 0; ks < 2; ks++) {
        const int ko = ks * 16;
        const uint32_t aoff = (uint32_t)((wm + (lane & 15)) * RS + ko + (lane >> 4) * 8) * 2;
        const uint32_t boff = (uint32_t)((wn + ((lane >> 4) & 1) * 8 + (lane & 7)) * RS
                                         + ko + ((lane >> 3) & 1) * 8) * 2;
        uint32_t af[4][4], bf[2][4];
        #pragma unroll
        for (int i = 0; i < 4; i++) ldm_x4(af[i], saHI + aoff + i * 16 * RS * 2);
        #pragma unroll
        for (int p = 0; p < 2; p++) ldm_x4(bf[p], sbHI + boff + p * 16 * RS * 2);
        #pragma unroll
        for (int i = 0; i < 4; i++)
            #pragma unroll
            for (int j = 0; j < 4; j++)
                mma16816(acc[i][j], af[i], &bf[j >> 1][(j & 1) * 2]);
        if (TERMS == 3) {
            uint32_t bl[2][4];
            #pragma unroll
            for (int p = 0; p < 2; p++) ldm_x4(bl[p], sbLO + boff + p * 16 * RS * 2);
            #pragma unroll
            for (int i = 0; i < 4; i++)
                #pragma unroll
                for (int j = 0; j < 4; j++)
                    mma16816(acc[i][j], af[i], &bl[j >> 1][(j & 1) * 2]);
            #pragma unroll
            for (int i = 0; i < 4; i++) ldm_x4(af[i], saLO + aoff + i * 16 * RS * 2);
            #pragma unroll
            for (int i = 0; i < 4; i++)
                #pragma unroll
                for (int j = 0; j < 4; j++)
                    mma16816(acc[i][j], af[i], &bf[j >> 1][(j & 1) * 2]);
        }
    }
}

// ================= generic HMMA GEMM (R5-proven 2-stage mainloop) ============
// C[M,N] = Ahl[M,K] @ Bhl[N,K]^T.  TERMS: 1 or 3.
// EPI: 0=f32+bias, 1=f32+bias+resid, 3=bf16 raw.  Grid: x=row, y=col (proven).
template<int TERMS, int EPI>
__global__ __launch_bounds__(256) void k_mma_gemm(
    const __nv_bfloat16* __restrict__ Ahi, const __nv_bfloat16* __restrict__ Alo,
    const __nv_bfloat16* __restrict__ Bhi, const __nv_bfloat16* __restrict__ Blo,
    const float* __restrict__ bias, const float* __restrict__ resid,
    void* __restrict__ Cv, int K, int ldc)
{
    extern __shared__ char smem[];
    constexpr int NTILES = (TERMS == 3) ? 4 : 2;
    constexpr int STAGE  = TILE_B * NTILES;
    const uint32_t sb = smem_u32(smem);
    const int tid = threadIdx.x, wid = tid >> 5, lane = tid & 31;
    const int row0 = blockIdx.x * 128;
    const int col0 = blockIdx.y * 128;
    const int wm = (wid >> 2) * 64, wn = (wid & 3) * 32;

    float acc[4][4][4] = {};
    const int NKB = K / 32;

    auto load_stage = [&](int s, int kb) {
        const int kpos = kb * 32;
        const uint32_t sbase = sb + s * STAGE;
        #pragma unroll
        for (int i = 0; i < 2; i++) {
            const int idx = tid + i * 256;
            const int r = idx >> 2, c = idx & 3;
            const uint32_t so = r * (RS * 2) + c * 16;
            const size_t gA = (size_t)(row0 + r) * K + kpos + c * 8;
            const size_t gB = (size_t)(col0 + r) * K + kpos + c * 8;
            cp16(sbase + 0 * TILE_B + so, Ahi + gA);
            if (TERMS == 3) {
                cp16(sbase + 1 * TILE_B + so, Alo + gA);
                cp16(sbase + 2 * TILE_B + so, Bhi + gB);
                cp16(sbase + 3 * TILE_B + so, Blo + gB);
            } else {
                cp16(sbase + 1 * TILE_B + so, Bhi + gB);
            }
        }
    };

    load_stage(0, 0); CP_COMMIT();

    for (int kb = 0; kb < NKB; kb++) {
        const int s = kb & 1;
        if (kb + 1 < NKB) { load_stage(s ^ 1, kb + 1); CP_COMMIT(); CP_WAIT(1); }
        else              { CP_WAIT(0); }
        __syncthreads();
        compute_block<TERMS>(acc, sb + s * STAGE, wm, wn, lane);
        __syncthreads();
    }

    // ---- epilogue --------------------------------------------------------
    const int g  = lane >> 2;
    const int tg = (lane & 3) * 2;
    #pragma unroll
    for (int i = 0; i < 4; i++) {
        #pragma unroll
        for (int j = 0; j < 4; j++) {
            const int r = row0 + wm + i * 16 + g;
            const int c = col0 + wn + j * 8 + tg;
            float v0 = acc[i][j][0], v1 = acc[i][j][1];
            float v2 = acc[i][j][2], v3 = acc[i][j][3];
            if (EPI == 0 || EPI == 1) {
                const float b0 = bias[c], b1 = bias[c + 1];
                v0 += b0; v1 += b1; v2 += b0; v3 += b1;
            }
            if (EPI == 1) {
                const float2 r0 = *(const float2*)&resid[(size_t)r * ldc + c];
                const float2 r1 = *(const float2*)&resid[(size_t)(r + 8) * ldc + c];
                v0 += r0.x; v1 += r0.y; v2 += r1.x; v3 += r1.y;
            }
            if (EPI == 3) {
                __nv_bfloat16* C = (__nv_bfloat16*)Cv;
                __nv_bfloat162 o0 = __floats2bfloat162_rn(v0, v1);
                __nv_bfloat162 o1 = __floats2bfloat162_rn(v2, v3);
                *(__nv_bfloat162*)&C[(size_t)r * ldc + c]       = o0;
                *(__nv_bfloat162*)&C[(size_t)(r + 8) * ldc + c] = o1;
            } else {
                float* C = (float*)Cv;
                float2 o0 = {v0, v1}, o1 = {v2, v3};
                *(float2*)&C[(size_t)r * ldc + c]       = o0;
                *(float2*)&C[(size_t)(r + 8) * ldc + c] = o1;
            }
        }
    }
}

// ========== GEMM1 with fused A-side f32->(hi,lo) conversion ==================
// proj[NPAD,DIM] = expr[NREF,GENES](f32, unpadded) @ W1t[DIM,KPAD1]^T + b1
// A tile: each thread LDGs 16 consecutive f32 (L1 absorbs per-instr spread),
// splits in regs, STS packed bf16. B (W1 hi/lo) via cp.async.
// 2-stage, 81920 B smem -> 2 CTAs/SM. Unswapped grid (x = row blocks).
__global__ __launch_bounds__(256, 2) void k_gemm1_fused(
    const float* __restrict__ expr,
    const __nv_bfloat16* __restrict__ Bhi, const __nv_bfloat16* __restrict__ Blo,
    const float* __restrict__ bias, float* __restrict__ C)
{
    extern __shared__ char smem[];
    constexpr int STAGE = TILE_B * 4;         // Ahi, Alo, Bhi, Blo
    const uint32_t sb = smem_u32(smem);
    const int tid = threadIdx.x, wid = tid >> 5, lane = tid & 31;
    const int row0 = blockIdx.x * 128;        // UNSWAPPED (proven layout)
    const int col0 = blockIdx.y * 128;
    const int wm = (wid >> 2) * 64, wn = (wid & 3) * 32;

    float acc[4][4][4] = {};
    const int NKB = KPAD1 / 32;               // 110

    // A-loader geometry: thread -> (row r, 16-col half ch), 16 consecutive f32
    const int ar = tid >> 1;
    const int ach = (tid & 1) * 16;
    const bool rowok = (row0 + ar) < NREF;
    const float* __restrict__ arow = expr + (size_t)(row0 + ar) * GENES + ach;

    auto ldgA = [&](int kb, float* v) {
        const int kpos = kb * 32;
        #pragma unroll
        for (int i = 0; i < 16; i++) {
            const int cg = kpos + ach + i;
            v[i] = (rowok && cg < GENES) ? __ldg(arow + kpos + i) : 0.0f;
        }
    };
    auto stsA = [&](int s, const float* v) {
        __align__(16) __nv_bfloat16 h[16], l[16];
        #pragma unroll
        for (int i = 0; i < 16; i++) split2(v[i], h[i], l[i]);
        const uint32_t so = (uint32_t)(ar * (RS * 2) + ach * 2);
        const uint32_t off = s * STAGE;
        *(uint4*)(smem + off + 0 * TILE_B + so)      = *(const uint4*)&h[0];
        *(uint4*)(smem + off + 0 * TILE_B + so + 16) = *(const uint4*)&h[8];
        *(uint4*)(smem + off + 1 * TILE_B + so)      = *(const uint4*)&l[0];
        *(uint4*)(smem + off + 1 * TILE_B + so + 16) = *(const uint4*)&l[8];
    };
    auto loadB = [&](int s, int kb) {
        const int kpos = kb * 32;
        const uint32_t sbase = sb + s * STAGE;
        #pragma unroll
        for (int i = 0; i < 2; i++) {
            const int idx = tid + i * 256;
            const int r = idx >> 2, c = idx & 3;
            const uint32_t so = r * (RS * 2) + c * 16;
            const size_t gB = (size_t)(col0 + r) * KPAD1 + kpos + c * 8;
            cp16(sbase + 2 * TILE_B + so, Bhi + gB);
            cp16(sbase + 3 * TILE_B + so, Blo + gB);
        }
    };

    float av[16];
    ldgA(0, av);
    loadB(0, 0); CP_COMMIT();

    for (int kb = 0; kb < NKB; kb++) {
        const int s = kb & 1;
        CP_WAIT(0);                     // B(kb) landed
        __syncthreads();                // stage s free (compute kb-2 done)
        stsA(s, av);                    // A(kb) regs -> smem
        if (kb + 1 < NKB) {
            loadB(s ^ 1, kb + 1); CP_COMMIT();
            ldgA(kb + 1, av);           // latency hidden under compute(kb)
        }
        __syncthreads();                // A STS visible
        compute_block<3>(acc, sb + s * STAGE, wm, wn, lane);
    }

    // epilogue: f32 + bias
    const int g  = lane >> 2;
    const int tg = (lane & 3) * 2;
    #pragma unroll
    for (int i = 0; i < 4; i++) {
        #pragma unroll
        for (int j = 0; j < 4; j++) {
            const int r = row0 + wm + i * 16 + g;
            const int c = col0 + wn + j * 8 + tg;
            const float b0 = bias[c], b1 = bias[c + 1];
            float2 o0 = {acc[i][j][0] + b0, acc[i][j][1] + b1};
            float2 o1 = {acc[i][j][2] + b0, acc[i][j][3] + b1};
            *(float2*)&C[(size_t)r * DIM + c]       = o0;
            *(float2*)&C[(size_t)(r + 8) * DIM + c] = o1;
        }
    }
}

// ================= conversion / split kernels ================================
// transpose+split W[K,N] -> out[N, KP] K-major
__global__ __launch_bounds__(256) void k_split_wt(const float* __restrict__ W,
    __nv_bfloat16* __restrict__ hi, __nv_bfloat16* __restrict__ lo, int Kreal, int KP)
{
    const long long idx = (long long)blockIdx.x * 256 + threadIdx.x;
    if (idx >= (long long)DIM * KP) return;
    const int n = (int)(idx / KP);
    const int k = (int)(idx % KP);
    const float v = (k < Kreal) ? W[(size_t)k * DIM + n] : 0.0f;
    __nv_bfloat16 h, l;
    split2(v, h, l);
    hi[idx] = h; lo[idx] = l;
}

__global__ __launch_bounds__(256) void k_gelu_split(const float* __restrict__ P,
    __nv_bfloat16* __restrict__ hi, __nv_bfloat16* __restrict__ lo)
{
    const size_t idx = (size_t)blockIdx.x * 256 + threadIdx.x;
    if (idx >= (size_t)NPAD * DIM) return;
    __nv_bfloat16 h, l;
    split2(gelu_exact(P[idx]), h, l);
    hi[idx] = h; lo[idx] = l;
}

__global__ __launch_bounds__(256) void k_split_q(const float* __restrict__ q,
    __nv_bfloat16* __restrict__ hi)
{
    const size_t idx = (size_t)blockIdx.x * 256 + threadIdx.x;
    if (idx >= (size_t)NQ * DIM) return;
    hi[idx] = __float2bfloat16(q[idx]);
}

// --------- LayerNorm (in place) + 1/||row|| + fused bf16 normalized copy ----
__global__ __launch_bounds__(128) void k_ln(
    float* __restrict__ h, const float* __restrict__ gamma,
    const float* __restrict__ beta, float* __restrict__ rnorm,
    __nv_bfloat16* __restrict__ embn)
{
    const int row = blockIdx.x;
    const int tid = threadIdx.x;
    if (row >= NREF) {                          // padded rows: zero embn only
        uint2 z = {0u, 0u};
        ((uint2*)(embn + (size_t)row * DIM))[tid] = z;
        return;
    }
    const int lane = tid & 31, warp = tid >> 5;
    __shared__ float red[4];

    float4 v = ((const float4*)(h + (size_t)row * DIM))[tid];
    float s = v.x + v.y + v.z + v.w;
    #pragma unroll
    for (int o = 16; o; o >>= 1) s += __shfl_xor_sync(0xFFFFFFFFu, s, o);
    if (lane == 0) red[warp] = s;
    __syncthreads();
    const float mu = (red[0] + red[1] + red[2] + red[3]) * (1.0f / DIM);
    __syncthreads();
    float dx = v.x - mu, dy = v.y - mu, dz = v.z - mu, dw = v.w - mu;
    float s2 = dx*dx + dy*dy + dz*dz + dw*dw;
    #pragma unroll
    for (int o = 16; o; o >>= 1) s2 += __shfl_xor_sync(0xFFFFFFFFu, s2, o);
    if (lane == 0) red[warp] = s2;
    __syncthreads();
    const float var = (red[0] + red[1] + red[2] + red[3]) * (1.0f / DIM);
    __syncthreads();
    const float rs = rsqrtf(var + LN_EPS);
    const int c = tid * 4;
    float4 y;
    y.x = dx * rs * gamma[c + 0] + beta[c + 0];
    y.y = dy * rs * gamma[c + 1] + beta[c + 1];
    y.z = dz * rs * gamma[c + 2] + beta[c + 2];
    y.w = dw * rs * gamma[c + 3] + beta[c + 3];
    float n2 = y.x*y.x + y.y*y.y + y.z*y.z + y.w*y.w;
    #pragma unroll
    for (int o = 16; o; o >>= 1) n2 += __shfl_xor_sync(0xFFFFFFFFu, n2, o);
    if (lane == 0) red[warp] = n2;
    __syncthreads();
    const float rn = rsqrtf(red[0] + red[1] + red[2] + red[3]);
    if (tid == 0) rnorm[row] = rn;
    ((float4*)(h + (size_t)row * DIM))[tid] = y;
    __nv_bfloat162 e0 = __floats2bfloat162_rn(y.x * rn, y.y * rn);
    __nv_bfloat162 e1 = __floats2bfloat162_rn(y.z * rn, y.w * rn);
    *(__nv_bfloat162*)(embn + (size_t)row * DIM + c)     = e0;
    *(__nv_bfloat162*)(embn + (size_t)row * DIM + c + 2) = e1;
}

// ---------------- top-50: 2 global passes (bf16 keys) + smem radix refine ---
__device__ __forceinline__ unsigned f2key(float v) {
    unsigned u = __float_as_uint(v);
    return (u & 0x80000000u) ? ~u : (u | 0x80000000u);   // monotone increasing
}

#define TKBINS   2048
#define CAND_CAP 4096
__global__ __launch_bounds__(256) void k_topk(
    const __nv_bfloat16* __restrict__ sim, int* __restrict__ out_idx)
{
    const int q = blockIdx.x;
    const int tid = threadIdx.x;
    const __nv_bfloat16* __restrict__ row = sim + (size_t)q * NPAD;

    __shared__ unsigned hist[TKBINS];
    __shared__ unsigned csum[256];
    __shared__ unsigned ckey[CAND_CAP];
    __shared__ int      cidx[CAND_CAP];
    __shared__ int sh_bin, cnt, sh_want, cnt2;
    __shared__ unsigned sh_prefix;

    for (int i = tid; i < TKBINS; i += 256) hist[i] = 0;
    __syncthreads();
    for (int j = tid; j < NREF; j += 256)
        atomicAdd(&hist[f2key(__bfloat162float(row[j])) >> 21], 1u);
    __syncthreads();
    unsigned s = 0;
    #pragma unroll
    for (int b = 0; b < 8; b++) s += hist[tid * 8 + b];
    csum[tid] = s;
    __syncthreads();
    if (tid == 0) {
        unsigned cum = 0; int chunk = 255;
        for (; chunk > 0; chunk--) { if (cum + csum[chunk] >= TOPK) break; cum += csum[chunk]; }
        int b = chunk * 8 + 7;
        unsigned c2 = cum;
        for (; b > chunk * 8; b--) { if (c2 + hist[b] >= TOPK) break; c2 += hist[b]; }
        sh_bin = b;
        cnt = 0;
    }
    __syncthreads();
    const unsigned binT = (unsigned)sh_bin;

    for (int j = tid; j < NREF; j += 256) {
        const unsigned k = f2key(__bfloat162float(row[j]));
        if ((k >> 21) >= binT) {
            const int p = atomicAdd(&cnt, 1);
            if (p < CAND_CAP) { ckey[p] = k; cidx[p] = j; }
        }
    }
    __syncthreads();
    const int L = min(cnt, CAND_CAP);

    unsigned prefix = 0; int want = TOPK;
    #pragma unroll 1
    for (int p = 3; p >= 0; --p) {
        __syncthreads();
        if (tid < 256) hist[tid] = 0;
        __syncthreads();
        for (int i = tid; i < L; i += 256) {
            const unsigned k = ckey[i];
            if (p == 3 || (k >> ((p + 1) * 8)) == prefix)
                atomicAdd(&hist[(k >> (p * 8)) & 255u], 1u);
        }
        __syncthreads();
        if (tid == 0) {
            unsigned cum = 0;
            for (int b = 255; b >= 0; --b) {
                cum += hist[b];
                if ((int)cum >= want) {
                    sh_want = want - (int)(cum - hist[b]);
                    sh_prefix = (prefix << 8) | (unsigned)b;
                    break;
                }
            }
            cnt2 = 0;
        }
        __syncthreads();
        prefix = sh_prefix;
        want = sh_want;
    }
    const unsigned T = prefix;

    for (int i = tid; i < L; i += 256) {
        if (ckey[i] > T) {
            const int p = atomicAdd(&cnt2, 1);
            if (p < TOPK) out_idx[q * TOPK + p] = cidx[i];
        }
    }
    __syncthreads();
    for (int i = tid; i < L; i += 256) {
        if (ckey[i] == T) {
            const int p = atomicAdd(&cnt2, 1);
            if (p < TOPK) out_idx[q * TOPK + p] = cidx[i];
        }
    }
}

// ---------------- distances + weights + weighted expression mean ------------
__global__ __launch_bounds__(256) void k_predict(
    const float* __restrict__ qf, const float* __restrict__ expr,
    const float* __restrict__ emb, const int* __restrict__ idx,
    float* __restrict__ out)
{
    const int q = blockIdx.x;
    const int tid = threadIdx.x;
    const int lane = tid & 31, warp = tid >> 5;

    __shared__ float sq[DIM];
    __shared__ int   sidx[TOPK];
    __shared__ float swt[TOPK];
    __shared__ float s_invw;

    for (int c = tid; c < DIM; c += 256) sq[c] = qf[(size_t)q * DIM + c];
    if (tid < TOPK) sidx[tid] = idx[q * TOPK + tid];
    __syncthreads();

    for (int k = warp; k < TOPK; k += 8) {
        const float* __restrict__ e = emb + (size_t)sidx[k] * DIM;
        float s = 0.0f;
        for (int c = lane; c < DIM; c += 32) {
            const float d = e[c] - sq[c];
            s = fmaf(d, d, s);
        }
        #pragma unroll
        for (int o = 16; o; o >>= 1) s += __shfl_xor_sync(0xFFFFFFFFu, s, o);
        if (lane == 0) swt[k] = s;
    }
    __syncthreads();

    if (tid == 0) {
        // anchor at min distance: pred is exactly invariant to anchor choice
        float a = swt[0];
        for (int k = 1; k < TOPK; k++) a = fminf(a, swt[k]);
        float sw = 0.0f;
        for (int k = 0; k < TOPK; k++) {
            const float w = expf(-(swt[k] - a + 1.0f));
            swt[k] = w;
            sw += w;
        }
        s_invw = 1.0f / sw;
    }
    __syncthreads();

    const float inv = s_invw;
    for (int g = tid; g < GENES; g += 256) {
        float acc = 0.0f;
        #pragma unroll 10
        for (int k = 0; k < TOPK; k++)
            acc = fmaf(swt[k], expr[(size_t)sidx[k] * GENES + g], acc);
        out[(size_t)q * GENES + g] = acc * inv;
    }
}

// ---------------- launch ----------------------------------------------------
extern "C" void kernel_launch(void* const* d_in, const int* in_sizes, int n_in,
                              void* d_out, int out_size)
{
    const float* imgf  = (const float*)d_in[0];
    const float* expr  = (const float*)d_in[1];
    const float* W1    = (const float*)d_in[2];
    const float* b1    = (const float*)d_in[3];
    const float* W2    = (const float*)d_in[4];
    const float* b2    = (const float*)d_in[5];
    const float* gamma = (const float*)d_in[6];
    const float* beta  = (const float*)d_in[7];
    float* out = (float*)d_out;

    __nv_bfloat16 *w1h, *w1l, *w2h, *w2l, *gh, *gl, *embn, *qh, *sim;
    float *proj, *emb, *rnorm;
    int *idxp;
    cudaGetSymbolAddress((void**)&w1h,  g_w1t_hi);
    cudaGetSymbolAddress((void**)&w1l,  g_w1t_lo);
    cudaGetSymbolAddress((void**)&w2h,  g_w2t_hi);
    cudaGetSymbolAddress((void**)&w2l,  g_w2t_lo);
    cudaGetSymbolAddress((void**)&gh,   g_g_hi);
    cudaGetSymbolAddress((void**)&gl,   g_g_lo);
    cudaGetSymbolAddress((void**)&embn, g_embn);
    cudaGetSymbolAddress((void**)&qh,   g_qhi);
    cudaGetSymbolAddress((void**)&sim,  g_sim);
    cudaGetSymbolAddress((void**)&proj, g_proj);
    cudaGetSymbolAddress((void**)&emb,  g_emb);
    cudaGetSymbolAddress((void**)&rnorm,g_rnorm);
    cudaGetSymbolAddress((void**)&idxp, g_idx);

    const int SM3 = 2 * 4 * TILE_B;   // 81920 B -> 2 CTAs/SM (proven)
    const int SM1 = 2 * 2 * TILE_B;   // 40960 B
    cudaFuncSetAttribute(k_gemm1_fused,   cudaFuncAttributeMaxDynamicSharedMemorySize, SM3);
    cudaFuncSetAttribute(k_mma_gemm<3,1>, cudaFuncAttributeMaxDynamicSharedMemorySize, SM3);
    cudaFuncSetAttribute(k_mma_gemm<1,3>, cudaFuncAttributeMaxDynamicSharedMemorySize, SM1);

    // 0) weight splits / q conversion (small)
    k_split_wt<<<(unsigned)(((size_t)DIM * KPAD1 + 255) / 256), 256>>>(W1, w1h, w1l, GENES, KPAD1);
    k_split_wt<<<(unsigned)(((size_t)DIM * DIM + 255) / 256), 256>>>(W2, w2h, w2l, DIM, DIM);
    k_split_q<<<(unsigned)(((size_t)NQ * DIM + 255) / 256), 256>>>(imgf, qh);

    // 1) proj = expr @ W1 + b1  (fused f32->hi/lo in loader; unswapped grid)
    k_gemm1_fused<<<dim3(NPAD / 128, DIM / 128), 256, SM3>>>(expr, w1h, w1l, b1, proj);

    // 2) gelu(proj) split
    k_gelu_split<<<(unsigned)(((size_t)NPAD * DIM + 255) / 256), 256>>>(proj, gh, gl);

    // 3) emb = gelu(proj) @ W2 + b2 + proj   (R5 grid)
    k_mma_gemm<3,1><<<dim3(NPAD / 128, DIM / 128), 256, SM3>>>(
        gh, gl, w2h, w2l, b2, proj, emb, DIM, DIM);

    // 4) LayerNorm in place + 1/||row|| + fused bf16 normalized emb
    k_ln<<<NPAD, 128>>>(emb, gamma, beta, rnorm, embn);

    // 5) sim = q @ embn^T  (1-term bf16, bf16 keys out; R5 grid)
    k_mma_gemm<1,3><<<dim3(NQ / 128, NPAD / 128), 256, SM1>>>(
        qh, qh, embn, embn, nullptr, nullptr, sim, DIM, NPAD);

    // 6) exact top-50 set per query (on bf16 keys)
    k_topk<<<NQ, 256>>>(sim, idxp);

    // 7) distances -> weights -> weighted gene means
    k_predict<<<NQ, 256>>>(imgf, expr, emb, idxp, out);
}

// round 12
// speedup vs baseline: 1.0951x; 1.0951x over previous
#include <cuda_runtime.h>
#include <cuda_bf16.h>
#include <math.h>
#include <stdint.h>

#define NQ    2048
#define NREF  100000
#define GENES 3467
#define DIM   512
#define TOPK  50
#define LN_EPS 1e-5f

#define KPAD1 3520          // GENES padded to mult of 32
#define NPAD  100352        // NREF padded to mult of 128
#define RS    40            // smem row stride in bf16 (80B, conflict-free ldmatrix)

// ---------------- scratch (device globals; no allocation allowed) ----------
__device__ __nv_bfloat16 g_expr_hi[(size_t)NPAD * KPAD1];
__device__ __nv_bfloat16 g_expr_lo[(size_t)NPAD * KPAD1];
__device__ __nv_bfloat16 g_w1t_hi[(size_t)DIM * KPAD1];
__device__ __nv_bfloat16 g_w1t_lo[(size_t)DIM * KPAD1];
__device__ __nv_bfloat16 g_w2t_hi[(size_t)DIM * DIM];
__device__ __nv_bfloat16 g_w2t_lo[(size_t)DIM * DIM];
__device__ __nv_bfloat16 g_g_hi[(size_t)NPAD * DIM];
__device__ __nv_bfloat16 g_g_lo[(size_t)NPAD * DIM];
__device__ __nv_bfloat16 g_embn[(size_t)NPAD * DIM];
__device__ __nv_bfloat16 g_qhi[(size_t)NQ * DIM];
__device__ float g_proj[(size_t)NPAD * DIM];
__device__ float g_emb [(size_t)NPAD * DIM];
__device__ float g_rnorm[NREF];
__device__ __nv_bfloat16 g_sim [(size_t)NQ * NPAD];   // bf16 ranking keys
__device__ int   g_idx [NQ * TOPK];

// ---------------- PTX helpers (base compute_103 features only) --------------
__device__ __forceinline__ uint32_t smem_u32(const void* p) {
    uint32_t a;
    asm("{ .reg .u64 t; cvta.to.shared.u64 t, %1; cvt.u32.u64 %0, t; }" : "=r"(a) : "l"(p));
    return a;
}
__device__ __forceinline__ void cp16(uint32_t sa, const void* ga) {
    asm volatile("cp.async.cg.shared.global [%0], [%1], 16;" :: "r"(sa), "l"(ga));
}
#define CP_COMMIT() asm volatile("cp.async.commit_group;" ::: "memory")
#define CP_WAIT(n)  asm volatile("cp.async.wait_group %0;" :: "n"(n) : "memory")

__device__ __forceinline__ void ldm_x4(uint32_t* r, uint32_t addr) {
    asm volatile("ldmatrix.sync.aligned.m8n8.x4.shared.b16 {%0,%1,%2,%3}, [%4];"
        : "=r"(r[0]), "=r"(r[1]), "=r"(r[2]), "=r"(r[3]) : "r"(addr));
}
__device__ __forceinline__ void mma16816(float* d, const uint32_t* a, const uint32_t* b) {
    asm volatile(
        "mma.sync.aligned.m16n8k16.row.col.f32.bf16.bf16.f32 "
        "{%0,%1,%2,%3}, {%4,%5,%6,%7}, {%8,%9}, {%0,%1,%2,%3};"
        : "+f"(d[0]), "+f"(d[1]), "+f"(d[2]), "+f"(d[3])
        : "r"(a[0]), "r"(a[1]), "r"(a[2]), "r"(a[3]), "r"(b[0]), "r"(b[1]));
}

// ---------------- bf16 split helpers ----------------------------------------
__device__ __forceinline__ void split2(float x, __nv_bfloat16& h, __nv_bfloat16& l) {
    h = __float2bfloat16(x);
    l = __float2bfloat16(x - __bfloat162float(h));
}
__device__ __forceinline__ float gelu_exact(float x) {
    return 0.5f * x * (1.0f + erff(x * 0.70710678118654752f));
}

#define TILE_B (128 * RS * 2)   // 10240 bytes per tile

// ---- shared compute core: one BK=32 block, 3-term or 1-term -----------------
template<int TERMS>
__device__ __forceinline__ void compute_block(
    float acc[4][4][4], uint32_t sbase, int wm, int wn, int lane)
{
    const uint32_t saHI = sbase;
    const uint32_t saLO = sbase + TILE_B;
    const uint32_t sbHI = sbase + ((TERMS == 3) ? 2 : 1) * TILE_B;
    const uint32_t sbLO = sbase + 3 * TILE_B;
    #pragma unroll
    for (int ks = 0; ks < 2; ks++) {
        const int ko = ks * 16;
        const uint32_t aoff = (uint32_t)((wm + (lane & 15)) * RS + ko + (lane >> 4) * 8) * 2;
        const uint32_t boff = (uint32_t)((wn + ((lane >> 4) & 1) * 8 + (lane & 7)) * RS
                                         + ko + ((lane >> 3) & 1) * 8) * 2;
        uint32_t af[4][4], bf[2][4];
        #pragma unroll
        for (int i = 0; i < 4; i++) ldm_x4(af[i], saHI + aoff + i * 16 * RS * 2);
        #pragma unroll
        for (int p = 0; p < 2; p++) ldm_x4(bf[p], sbHI + boff + p * 16 * RS * 2);
        #pragma unroll
        for (int i = 0; i < 4; i++)
            #pragma unroll
            for (int j = 0; j < 4; j++)
                mma16816(acc[i][j], af[i], &bf[j >> 1][(j & 1) * 2]);
        if (TERMS == 3) {
            uint32_t bl[2][4];
            #pragma unroll
            for (int p = 0; p < 2; p++) ldm_x4(bl[p], sbLO + boff + p * 16 * RS * 2);
            #pragma unroll
            for (int i = 0; i < 4; i++)
                #pragma unroll
                for (int j = 0; j < 4; j++)
                    mma16816(acc[i][j], af[i], &bl[j >> 1][(j & 1) * 2]);
            #pragma unroll
            for (int i = 0; i < 4; i++) ldm_x4(af[i], saLO + aoff + i * 16 * RS * 2);
            #pragma unroll
            for (int i = 0; i < 4; i++)
                #pragma unroll
                for (int j = 0; j < 4; j++)
                    mma16816(acc[i][j], af[i], &bf[j >> 1][(j & 1) * 2]);
        }
    }
}

// ================= generic HMMA GEMM — single-sync 2-stage mainloop ==========
// C[M,N] = Ahl[M,K] @ Bhl[N,K]^T.  TERMS: 1 or 3.
// EPI: 0=f32+bias, 1=f32+bias+resid, 3=bf16 raw.  Grid: x=row, y=col (proven).
// Loop order per iter: wait(kb) -> sync -> issue load(kb+1 into s^1) -> compute(s).
// The sync certifies all warps finished compute(kb-1) on s^1, so the overwrite
// is safe with ONE barrier per iteration (was two).
template<int TERMS, int EPI>
__global__ __launch_bounds__(256) void k_mma_gemm(
    const __nv_bfloat16* __restrict__ Ahi, const __nv_bfloat16* __restrict__ Alo,
    const __nv_bfloat16* __restrict__ Bhi, const __nv_bfloat16* __restrict__ Blo,
    const float* __restrict__ bias, const float* __restrict__ resid,
    void* __restrict__ Cv, int K, int ldc)
{
    extern __shared__ char smem[];
    constexpr int NTILES = (TERMS == 3) ? 4 : 2;
    constexpr int STAGE  = TILE_B * NTILES;
    const uint32_t sb = smem_u32(smem);
    const int tid = threadIdx.x, wid = tid >> 5, lane = tid & 31;
    const int row0 = blockIdx.x * 128;
    const int col0 = blockIdx.y * 128;
    const int wm = (wid >> 2) * 64, wn = (wid & 3) * 32;

    float acc[4][4][4] = {};
    const int NKB = K / 32;

    auto load_stage = [&](int s, int kb) {
        const int kpos = kb * 32;
        const uint32_t sbase = sb + s * STAGE;
        #pragma unroll
        for (int i = 0; i < 2; i++) {
            const int idx = tid + i * 256;
            const int r = idx >> 2, c = idx & 3;
            const uint32_t so = r * (RS * 2) + c * 16;
            const size_t gA = (size_t)(row0 + r) * K + kpos + c * 8;
            const size_t gB = (size_t)(col0 + r) * K + kpos + c * 8;
            cp16(sbase + 0 * TILE_B + so, Ahi + gA);
            if (TERMS == 3) {
                cp16(sbase + 1 * TILE_B + so, Alo + gA);
                cp16(sbase + 2 * TILE_B + so, Bhi + gB);
                cp16(sbase + 3 * TILE_B + so, Blo + gB);
            } else {
                cp16(sbase + 1 * TILE_B + so, Bhi + gB);
            }
        }
    };

    load_stage(0, 0); CP_COMMIT();

    for (int kb = 0; kb < NKB; kb++) {
        const int s = kb & 1;
        CP_WAIT(0);                       // group(kb) landed (only one in flight)
        __syncthreads();                  // all warps done computing stage s^1
        if (kb + 1 < NKB) { load_stage(s ^ 1, kb + 1); CP_COMMIT(); }
        compute_block<TERMS>(acc, sb + s * STAGE, wm, wn, lane);
    }

    // ---- epilogue (reads registers only; no smem reuse) -------------------
    const int g  = lane >> 2;
    const int tg = (lane & 3) * 2;
    #pragma unroll
    for (int i = 0; i < 4; i++) {
        #pragma unroll
        for (int j = 0; j < 4; j++) {
            const int r = row0 + wm + i * 16 + g;
            const int c = col0 + wn + j * 8 + tg;
            float v0 = acc[i][j][0], v1 = acc[i][j][1];
            float v2 = acc[i][j][2], v3 = acc[i][j][3];
            if (EPI == 0 || EPI == 1) {
                const float b0 = bias[c], b1 = bias[c + 1];
                v0 += b0; v1 += b1; v2 += b0; v3 += b1;
            }
            if (EPI == 1) {
                const float2 r0 = *(const float2*)&resid[(size_t)r * ldc + c];
                const float2 r1 = *(const float2*)&resid[(size_t)(r + 8) * ldc + c];
                v0 += r0.x; v1 += r0.y; v2 += r1.x; v3 += r1.y;
            }
            if (EPI == 3) {
                __nv_bfloat16* C = (__nv_bfloat16*)Cv;
                __nv_bfloat162 o0 = __floats2bfloat162_rn(v0, v1);
                __nv_bfloat162 o1 = __floats2bfloat162_rn(v2, v3);
                *(__nv_bfloat162*)&C[(size_t)r * ldc + c]       = o0;
                *(__nv_bfloat162*)&C[(size_t)(r + 8) * ldc + c] = o1;
            } else {
                float* C = (float*)Cv;
                float2 o0 = {v0, v1}, o1 = {v2, v3};
                *(float2*)&C[(size_t)r * ldc + c]       = o0;
                *(float2*)&C[(size_t)(r + 8) * ldc + c] = o1;
            }
        }
    }
}

// ================= conversion / split kernels ================================
__global__ __launch_bounds__(256) void k_split_expr(const float* __restrict__ X,
    __nv_bfloat16* __restrict__ hi, __nv_bfloat16* __restrict__ lo)
{
    const size_t idx4 = (size_t)blockIdx.x * 256 + threadIdx.x;
    if (idx4 >= (size_t)NPAD * (KPAD1 / 4)) return;
    const int j  = (int)(idx4 / (KPAD1 / 4));
    const int k0 = (int)(idx4 % (KPAD1 / 4)) * 4;
    __nv_bfloat16 h[4], l[4];
    #pragma unroll
    for (int i = 0; i < 4; i++) {
        const int k = k0 + i;
        const float v = (j < NREF && k < GENES) ? X[(size_t)j * GENES + k] : 0.0f;
        split2(v, h[i], l[i]);
    }
    *(uint2*)(hi + (size_t)j * KPAD1 + k0) = *(const uint2*)h;
    *(uint2*)(lo + (size_t)j * KPAD1 + k0) = *(const uint2*)l;
}

// transpose+split W[K,N] -> out[N, KP] K-major
__global__ __launch_bounds__(256) void k_split_wt(const float* __restrict__ W,
    __nv_bfloat16* __restrict__ hi, __nv_bfloat16* __restrict__ lo, int Kreal, int KP)
{
    const long long idx = (long long)blockIdx.x * 256 + threadIdx.x;
    if (idx >= (long long)DIM * KP) return;
    const int n = (int)(idx / KP);
    const int k = (int)(idx % KP);
    const float v = (k < Kreal) ? W[(size_t)k * DIM + n] : 0.0f;
    __nv_bfloat16 h, l;
    split2(v, h, l);
    hi[idx] = h; lo[idx] = l;
}

__global__ __launch_bounds__(256) void k_gelu_split(const float* __restrict__ P,
    __nv_bfloat16* __restrict__ hi, __nv_bfloat16* __restrict__ lo)
{
    const size_t idx = (size_t)blockIdx.x * 256 + threadIdx.x;
    if (idx >= (size_t)NPAD * DIM) return;
    __nv_bfloat16 h, l;
    split2(gelu_exact(P[idx]), h, l);
    hi[idx] = h; lo[idx] = l;
}

__global__ __launch_bounds__(256) void k_split_q(const float* __restrict__ q,
    __nv_bfloat16* __restrict__ hi)
{
    const size_t idx = (size_t)blockIdx.x * 256 + threadIdx.x;
    if (idx >= (size_t)NQ * DIM) return;
    hi[idx] = __float2bfloat16(q[idx]);
}

// --------- LayerNorm (in place) + 1/||row|| + fused bf16 normalized copy ----
__global__ __launch_bounds__(128) void k_ln(
    float* __restrict__ h, const float* __restrict__ gamma,
    const float* __restrict__ beta, float* __restrict__ rnorm,
    __nv_bfloat16* __restrict__ embn)
{
    const int row = blockIdx.x;
    const int tid = threadIdx.x;
    if (row >= NREF) {                          // padded rows: zero embn only
        uint2 z = {0u, 0u};
        ((uint2*)(embn + (size_t)row * DIM))[tid] = z;
        return;
    }
    const int lane = tid & 31, warp = tid >> 5;
    __shared__ float red[4];

    float4 v = ((const float4*)(h + (size_t)row * DIM))[tid];
    float s = v.x + v.y + v.z + v.w;
    #pragma unroll
    for (int o = 16; o; o >>= 1) s += __shfl_xor_sync(0xFFFFFFFFu, s, o);
    if (lane == 0) red[warp] = s;
    __syncthreads();
    const float mu = (red[0] + red[1] + red[2] + red[3]) * (1.0f / DIM);
    __syncthreads();
    float dx = v.x - mu, dy = v.y - mu, dz = v.z - mu, dw = v.w - mu;
    float s2 = dx*dx + dy*dy + dz*dz + dw*dw;
    #pragma unroll
    for (int o = 16; o; o >>= 1) s2 += __shfl_xor_sync(0xFFFFFFFFu, s2, o);
    if (lane == 0) red[warp] = s2;
    __syncthreads();
    const float var = (red[0] + red[1] + red[2] + red[3]) * (1.0f / DIM);
    __syncthreads();
    const float rs = rsqrtf(var + LN_EPS);
    const int c = tid * 4;
    float4 y;
    y.x = dx * rs * gamma[c + 0] + beta[c + 0];
    y.y = dy * rs * gamma[c + 1] + beta[c + 1];
    y.z = dz * rs * gamma[c + 2] + beta[c + 2];
    y.w = dw * rs * gamma[c + 3] + beta[c + 3];
    float n2 = y.x*y.x + y.y*y.y + y.z*y.z + y.w*y.w;
    #pragma unroll
    for (int o = 16; o; o >>= 1) n2 += __shfl_xor_sync(0xFFFFFFFFu, n2, o);
    if (lane == 0) red[warp] = n2;
    __syncthreads();
    const float rn = rsqrtf(red[0] + red[1] + red[2] + red[3]);
    if (tid == 0) rnorm[row] = rn;
    ((float4*)(h + (size_t)row * DIM))[tid] = y;
    __nv_bfloat162 e0 = __floats2bfloat162_rn(y.x * rn, y.y * rn);
    __nv_bfloat162 e1 = __floats2bfloat162_rn(y.z * rn, y.w * rn);
    *(__nv_bfloat162*)(embn + (size_t)row * DIM + c)     = e0;
    *(__nv_bfloat162*)(embn + (size_t)row * DIM + c + 2) = e1;
}

// ---------------- top-50: 2 global passes (bf16 keys) + smem radix refine ---
__device__ __forceinline__ unsigned f2key(float v) {
    unsigned u = __float_as_uint(v);
    return (u & 0x80000000u) ? ~u : (u | 0x80000000u);   // monotone increasing
}

#define TKBINS   2048
#define CAND_CAP 4096
__global__ __launch_bounds__(256) void k_topk(
    const __nv_bfloat16* __restrict__ sim, int* __restrict__ out_idx)
{
    const int q = blockIdx.x;
    const int tid = threadIdx.x;
    const __nv_bfloat16* __restrict__ row = sim + (size_t)q * NPAD;

    __shared__ unsigned hist[TKBINS];
    __shared__ unsigned csum[256];
    __shared__ unsigned ckey[CAND_CAP];
    __shared__ int      cidx[CAND_CAP];
    __shared__ int sh_bin, cnt, sh_want, cnt2;
    __shared__ unsigned sh_prefix;

    for (int i = tid; i < TKBINS; i += 256) hist[i] = 0;
    __syncthreads();
    for (int j = tid; j < NREF; j += 256)
        atomicAdd(&hist[f2key(__bfloat162float(row[j])) >> 21], 1u);
    __syncthreads();
    unsigned s = 0;
    #pragma unroll
    for (int b = 0; b < 8; b++) s += hist[tid * 8 + b];
    csum[tid] = s;
    __syncthreads();
    if (tid == 0) {
        unsigned cum = 0; int chunk = 255;
        for (; chunk > 0; chunk--) { if (cum + csum[chunk] >= TOPK) break; cum += csum[chunk]; }
        int b = chunk * 8 + 7;
        unsigned c2 = cum;
        for (; b > chunk * 8; b--) { if (c2 + hist[b] >= TOPK) break; c2 += hist[b]; }
        sh_bin = b;
        cnt = 0;
    }
    __syncthreads();
    const unsigned binT = (unsigned)sh_bin;

    for (int j = tid; j < NREF; j += 256) {
        const unsigned k = f2key(__bfloat162float(row[j]));
        if ((k >> 21) >= binT) {
            const int p = atomicAdd(&cnt, 1);
            if (p < CAND_CAP) { ckey[p] = k; cidx[p] = j; }
        }
    }
    __syncthreads();
    const int L = min(cnt, CAND_CAP);

    unsigned prefix = 0; int want = TOPK;
    #pragma unroll 1
    for (int p = 3; p >= 0; --p) {
        __syncthreads();
        if (tid < 256) hist[tid] = 0;
        __syncthreads();
        for (int i = tid; i < L; i += 256) {
            const unsigned k = ckey[i];
            if (p == 3 || (k >> ((p + 1) * 8)) == prefix)
                atomicAdd(&hist[(k >> (p * 8)) & 255u], 1u);
        }
        __syncthreads();
        if (tid == 0) {
            unsigned cum = 0;
            for (int b = 255; b >= 0; --b) {
                cum += hist[b];
                if ((int)cum >= want) {
                    sh_want = want - (int)(cum - hist[b]);
                    sh_prefix = (prefix << 8) | (unsigned)b;
                    break;
                }
            }
            cnt2 = 0;
        }
        __syncthreads();
        prefix = sh_prefix;
        want = sh_want;
    }
    const unsigned T = prefix;

    for (int i = tid; i < L; i += 256) {
        if (ckey[i] > T) {
            const int p = atomicAdd(&cnt2, 1);
            if (p < TOPK) out_idx[q * TOPK + p] = cidx[i];
        }
    }
    __syncthreads();
    for (int i = tid; i < L; i += 256) {
        if (ckey[i] == T) {
            const int p = atomicAdd(&cnt2, 1);
            if (p < TOPK) out_idx[q * TOPK + p] = cidx[i];
        }
    }
}

// ---------------- distances + weights + weighted expression mean ------------
__global__ __launch_bounds__(256) void k_predict(
    const float* __restrict__ qf, const float* __restrict__ expr,
    const float* __restrict__ emb, const int* __restrict__ idx,
    float* __restrict__ out)
{
    const int q = blockIdx.x;
    const int tid = threadIdx.x;
    const int lane = tid & 31, warp = tid >> 5;

    __shared__ float sq[DIM];
    __shared__ int   sidx[TOPK];
    __shared__ float swt[TOPK];
    __shared__ float s_invw;

    for (int c = tid; c < DIM; c += 256) sq[c] = qf[(size_t)q * DIM + c];
    if (tid < TOPK) sidx[tid] = idx[q * TOPK + tid];
    __syncthreads();

    for (int k = warp; k < TOPK; k += 8) {
        const float* __restrict__ e = emb + (size_t)sidx[k] * DIM;
        float s = 0.0f;
        for (int c = lane; c < DIM; c += 32) {
            const float d = e[c] - sq[c];
            s = fmaf(d, d, s);
        }
        #pragma unroll
        for (int o = 16; o; o >>= 1) s += __shfl_xor_sync(0xFFFFFFFFu, s, o);
        if (lane == 0) swt[k] = s;
    }
    __syncthreads();

    if (tid == 0) {
        // anchor at min distance: pred is exactly invariant to anchor choice
        float a = swt[0];
        for (int k = 1; k < TOPK; k++) a = fminf(a, swt[k]);
        float sw = 0.0f;
        for (int k = 0; k < TOPK; k++) {
            const float w = expf(-(swt[k] - a + 1.0f));
            swt[k] = w;
            sw += w;
        }
        s_invw = 1.0f / sw;
    }
    __syncthreads();

    const float inv = s_invw;
    for (int g = tid; g < GENES; g += 256) {
        float acc = 0.0f;
        #pragma unroll 10
        for (int k = 0; k < TOPK; k++)
            acc = fmaf(swt[k], expr[(size_t)sidx[k] * GENES + g], acc);
        out[(size_t)q * GENES + g] = acc * inv;
    }
}

// ---------------- launch ----------------------------------------------------
extern "C" void kernel_launch(void* const* d_in, const int* in_sizes, int n_in,
                              void* d_out, int out_size)
{
    const float* imgf  = (const float*)d_in[0];
    const float* expr  = (const float*)d_in[1];
    const float* W1    = (const float*)d_in[2];
    const float* b1    = (const float*)d_in[3];
    const float* W2    = (const float*)d_in[4];
    const float* b2    = (const float*)d_in[5];
    const float* gamma = (const float*)d_in[6];
    const float* beta  = (const float*)d_in[7];
    float* out = (float*)d_out;

    __nv_bfloat16 *eh, *el, *w1h, *w1l, *w2h, *w2l, *gh, *gl, *embn, *qh, *sim;
    float *proj, *emb, *rnorm;
    int *idxp;
    cudaGetSymbolAddress((void**)&eh,   g_expr_hi);
    cudaGetSymbolAddress((void**)&el,   g_expr_lo);
    cudaGetSymbolAddress((void**)&w1h,  g_w1t_hi);
    cudaGetSymbolAddress((void**)&w1l,  g_w1t_lo);
    cudaGetSymbolAddress((void**)&w2h,  g_w2t_hi);
    cudaGetSymbolAddress((void**)&w2l,  g_w2t_lo);
    cudaGetSymbolAddress((void**)&gh,   g_g_hi);
    cudaGetSymbolAddress((void**)&gl,   g_g_lo);
    cudaGetSymbolAddress((void**)&embn, g_embn);
    cudaGetSymbolAddress((void**)&qh,   g_qhi);
    cudaGetSymbolAddress((void**)&sim,  g_sim);
    cudaGetSymbolAddress((void**)&proj, g_proj);
    cudaGetSymbolAddress((void**)&emb,  g_emb);
    cudaGetSymbolAddress((void**)&rnorm,g_rnorm);
    cudaGetSymbolAddress((void**)&idxp, g_idx);

    const int SM3 = 2 * 4 * TILE_B;   // 81920 B -> 2 CTAs/SM (proven)
    const int SM1 = 2 * 2 * TILE_B;   // 40960 B
    cudaFuncSetAttribute(k_mma_gemm<3,0>, cudaFuncAttributeMaxDynamicSharedMemorySize, SM3);
    cudaFuncSetAttribute(k_mma_gemm<3,1>, cudaFuncAttributeMaxDynamicSharedMemorySize, SM3);
    cudaFuncSetAttribute(k_mma_gemm<1,3>, cudaFuncAttributeMaxDynamicSharedMemorySize, SM1);

    // 0) splits / conversions (proven coalesced split kernels)
    k_split_expr<<<(unsigned)(((size_t)NPAD * (KPAD1/4) + 255) / 256), 256>>>(expr, eh, el);
    k_split_wt<<<(unsigned)(((size_t)DIM * KPAD1 + 255) / 256), 256>>>(W1, w1h, w1l, GENES, KPAD1);
    k_split_wt<<<(unsigned)(((size_t)DIM * DIM + 255) / 256), 256>>>(W2, w2h, w2l, DIM, DIM);
    k_split_q<<<(unsigned)(((size_t)NQ * DIM + 255) / 256), 256>>>(imgf, qh);

    // 1) proj = expr @ W1 + b1   (3-term bf16; proven grid: x = row blocks)
    k_mma_gemm<3,0><<<dim3(NPAD / 128, DIM / 128), 256, SM3>>>(
        eh, el, w1h, w1l, b1, nullptr, proj, KPAD1, DIM);

    // 2) gelu(proj) split
    k_gelu_split<<<(unsigned)(((size_t)NPAD * DIM + 255) / 256), 256>>>(proj, gh, gl);

    // 3) emb = gelu(proj) @ W2 + b2 + proj
    k_mma_gemm<3,1><<<dim3(NPAD / 128, DIM / 128), 256, SM3>>>(
        gh, gl, w2h, w2l, b2, proj, emb, DIM, DIM);

    // 4) LayerNorm in place + 1/||row|| + fused bf16 normalized emb
    k_ln<<<NPAD, 128>>>(emb, gamma, beta, rnorm, embn);

    // 5) sim = q @ embn^T  (1-term bf16, bf16 keys out)
    k_mma_gemm<1,3><<<dim3(NQ / 128, NPAD / 128), 256, SM1>>>(
        qh, qh, embn, embn, nullptr, nullptr, sim, DIM, NPAD);

    // 6) exact top-50 set per query (on bf16 keys)
    k_topk<<<NQ, 256>>>(sim, idxp);

    // 7) distances -> weights -> weighted gene means
    k_predict<<<NQ, 256>>>(imgf, expr, emb, idxp, out);
}

// round 13
// speedup vs baseline: 1.1091x; 1.0128x over previous
#include <cuda_runtime.h>
#include <cuda_bf16.h>
#include <math.h>
#include <stdint.h>

#define NQ    2048
#define NREF  100000
#define GENES 3467
#define DIM   512
#define TOPK  50
#define LN_EPS 1e-5f

#define KPAD1 3520          // GENES padded to mult of 32
#define NPAD  100352        // NREF padded to mult of 128
#define RS    40            // smem row stride in bf16 (80B, conflict-free ldmatrix)

// ---------------- scratch (device globals; no allocation allowed) ----------
__device__ __nv_bfloat16 g_expr_hi[(size_t)NPAD * KPAD1];
__device__ __nv_bfloat16 g_expr_lo[(size_t)NPAD * KPAD1];
__device__ __nv_bfloat16 g_w1t_hi[(size_t)DIM * KPAD1];
__device__ __nv_bfloat16 g_w1t_lo[(size_t)DIM * KPAD1];
__device__ __nv_bfloat16 g_w2t_hi[(size_t)DIM * DIM];
__device__ __nv_bfloat16 g_w2t_lo[(size_t)DIM * DIM];
__device__ __nv_bfloat16 g_g_hi[(size_t)NPAD * DIM];
__device__ __nv_bfloat16 g_g_lo[(size_t)NPAD * DIM];
__device__ __nv_bfloat16 g_embn[(size_t)NPAD * DIM];
__device__ __nv_bfloat16 g_qhi[(size_t)NQ * DIM];
__device__ float g_proj[(size_t)NPAD * DIM];
__device__ float g_emb [(size_t)NPAD * DIM];
__device__ float g_rnorm[NREF];
__device__ __nv_bfloat16 g_sim [(size_t)NQ * NPAD];   // bf16 ranking keys
__device__ int   g_idx [NQ * TOPK];

// ---------------- PTX helpers (base compute_103 features only) --------------
__device__ __forceinline__ uint32_t smem_u32(const void* p) {
    uint32_t a;
    asm("{ .reg .u64 t; cvta.to.shared.u64 t, %1; cvt.u32.u64 %0, t; }" : "=r"(a) : "l"(p));
    return a;
}
__device__ __forceinline__ void cp16(uint32_t sa, const void* ga) {
    asm volatile("cp.async.cg.shared.global [%0], [%1], 16;" :: "r"(sa), "l"(ga));
}
#define CP_COMMIT() asm volatile("cp.async.commit_group;" ::: "memory")
#define CP_WAIT(n)  asm volatile("cp.async.wait_group %0;" :: "n"(n) : "memory")

__device__ __forceinline__ void ldm_x4(uint32_t* r, uint32_t addr) {
    asm volatile("ldmatrix.sync.aligned.m8n8.x4.shared.b16 {%0,%1,%2,%3}, [%4];"
        : "=r"(r[0]), "=r"(r[1]), "=r"(r[2]), "=r"(r[3]) : "r"(addr));
}
__device__ __forceinline__ void mma16816(float* d, const uint32_t* a, const uint32_t* b) {
    asm volatile(
        "mma.sync.aligned.m16n8k16.row.col.f32.bf16.bf16.f32 "
        "{%0,%1,%2,%3}, {%4,%5,%6,%7}, {%8,%9}, {%0,%1,%2,%3};"
        : "+f"(d[0]), "+f"(d[1]), "+f"(d[2]), "+f"(d[3])
        : "r"(a[0]), "r"(a[1]), "r"(a[2]), "r"(a[3]), "r"(b[0]), "r"(b[1]));
}

// ---------------- bf16 split helpers ----------------------------------------
__device__ __forceinline__ void split2(float x, __nv_bfloat16& h, __nv_bfloat16& l) {
    h = __float2bfloat16(x);
    l = __float2bfloat16(x - __bfloat162float(h));
}
__device__ __forceinline__ float gelu_exact(float x) {
    return 0.5f * x * (1.0f + erff(x * 0.70710678118654752f));
}

#define TILE_B (128 * RS * 2)   // 10240 bytes per tile

// ---- shared compute core: one BK=32 block, 3-term or 1-term -----------------
template<int TERMS>
__device__ __forceinline__ void compute_block(
    float acc[4][4][4], uint32_t sbase, int wm, int wn, int lane)
{
    const uint32_t saHI = sbase;
    const uint32_t saLO = sbase + TILE_B;
    const uint32_t sbHI = sbase + ((TERMS == 3) ? 2 : 1) * TILE_B;
    const uint32_t sbLO = sbase + 3 * TILE_B;
    #pragma unroll
    for (int ks = 0; ks < 2; ks++) {
        const int ko = ks * 16;
        const uint32_t aoff = (uint32_t)((wm + (lane & 15)) * RS + ko + (lane >> 4) * 8) * 2;
        const uint32_t boff = (uint32_t)((wn + ((lane >> 4) & 1) * 8 + (lane & 7)) * RS
                                         + ko + ((lane >> 3) & 1) * 8) * 2;
        uint32_t af[4][4], bf[2][4];
        #pragma unroll
        for (int i = 0; i < 4; i++) ldm_x4(af[i], saHI + aoff + i * 16 * RS * 2);
        #pragma unroll
        for (int p = 0; p < 2; p++) ldm_x4(bf[p], sbHI + boff + p * 16 * RS * 2);
        #pragma unroll
        for (int i = 0; i < 4; i++)
            #pragma unroll
            for (int j = 0; j < 4; j++)
                mma16816(acc[i][j], af[i], &bf[j >> 1][(j & 1) * 2]);
        if (TERMS == 3) {
            uint32_t bl[2][4];
            #pragma unroll
            for (int p = 0; p < 2; p++) ldm_x4(bl[p], sbLO + boff + p * 16 * RS * 2);
            #pragma unroll
            for (int i = 0; i < 4; i++)
                #pragma unroll
                for (int j = 0; j < 4; j++)
                    mma16816(acc[i][j], af[i], &bl[j >> 1][(j & 1) * 2]);
            #pragma unroll
            for (int i = 0; i < 4; i++) ldm_x4(af[i], saLO + aoff + i * 16 * RS * 2);
            #pragma unroll
            for (int i = 0; i < 4; i++)
                #pragma unroll
                for (int j = 0; j < 4; j++)
                    mma16816(acc[i][j], af[i], &bf[j >> 1][(j & 1) * 2]);
        }
    }
}

// ================= generic HMMA GEMM (R10-proven two-sync mainloop) ==========
// C[M,N] = Ahl[M,K] @ Bhl[N,K]^T.  TERMS: 1 or 3.
// EPI: 0=f32+bias, 1=f32+bias+resid, 3=bf16 raw.
// MAP: 0 -> row0=blockIdx.x, col0=blockIdx.y (plain, proven for sim)
//      2 -> serpentine pairs: row0=x>>1, col0=y*2+(x&1) (2-way in-wave A reuse)
template<int TERMS, int EPI, int MAP>
__global__ __launch_bounds__(256) void k_mma_gemm(
    const __nv_bfloat16* __restrict__ Ahi, const __nv_bfloat16* __restrict__ Alo,
    const __nv_bfloat16* __restrict__ Bhi, const __nv_bfloat16* __restrict__ Blo,
    const float* __restrict__ bias, const float* __restrict__ resid,
    void* __restrict__ Cv, int K, int ldc)
{
    extern __shared__ char smem[];
    constexpr int NTILES = (TERMS == 3) ? 4 : 2;
    constexpr int STAGE  = TILE_B * NTILES;
    const uint32_t sb = smem_u32(smem);
    const int tid = threadIdx.x, wid = tid >> 5, lane = tid & 31;
    int row0, col0;
    if (MAP == 2) {
        row0 = (int)(blockIdx.x >> 1) * 128;
        col0 = (int)(blockIdx.y * 2 + (blockIdx.x & 1)) * 128;
    } else {
        row0 = blockIdx.x * 128;
        col0 = blockIdx.y * 128;
    }
    const int wm = (wid >> 2) * 64, wn = (wid & 3) * 32;

    float acc[4][4][4] = {};
    const int NKB = K / 32;

    auto load_stage = [&](int s, int kb) {
        const int kpos = kb * 32;
        const uint32_t sbase = sb + s * STAGE;
        #pragma unroll
        for (int i = 0; i < 2; i++) {
            const int idx = tid + i * 256;
            const int r = idx >> 2, c = idx & 3;
            const uint32_t so = r * (RS * 2) + c * 16;
            const size_t gA = (size_t)(row0 + r) * K + kpos + c * 8;
            const size_t gB = (size_t)(col0 + r) * K + kpos + c * 8;
            cp16(sbase + 0 * TILE_B + so, Ahi + gA);
            if (TERMS == 3) {
                cp16(sbase + 1 * TILE_B + so, Alo + gA);
                cp16(sbase + 2 * TILE_B + so, Bhi + gB);
                cp16(sbase + 3 * TILE_B + so, Blo + gB);
            } else {
                cp16(sbase + 1 * TILE_B + so, Bhi + gB);
            }
        }
    };

    load_stage(0, 0); CP_COMMIT();

    for (int kb = 0; kb < NKB; kb++) {
        const int s = kb & 1;
        if (kb + 1 < NKB) { load_stage(s ^ 1, kb + 1); CP_COMMIT(); CP_WAIT(1); }
        else              { CP_WAIT(0); }
        __syncthreads();
        compute_block<TERMS>(acc, sb + s * STAGE, wm, wn, lane);
        __syncthreads();
    }

    // ---- epilogue --------------------------------------------------------
    const int g  = lane >> 2;
    const int tg = (lane & 3) * 2;
    #pragma unroll
    for (int i = 0; i < 4; i++) {
        #pragma unroll
        for (int j = 0; j < 4; j++) {
            const int r = row0 + wm + i * 16 + g;
            const int c = col0 + wn + j * 8 + tg;
            float v0 = acc[i][j][0], v1 = acc[i][j][1];
            float v2 = acc[i][j][2], v3 = acc[i][j][3];
            if (EPI == 0 || EPI == 1) {
                const float b0 = bias[c], b1 = bias[c + 1];
                v0 += b0; v1 += b1; v2 += b0; v3 += b1;
            }
            if (EPI == 1) {
                const float2 r0 = *(const float2*)&resid[(size_t)r * ldc + c];
                const float2 r1 = *(const float2*)&resid[(size_t)(r + 8) * ldc + c];
                v0 += r0.x; v1 += r0.y; v2 += r1.x; v3 += r1.y;
            }
            if (EPI == 3) {
                __nv_bfloat16* C = (__nv_bfloat16*)Cv;
                __nv_bfloat162 o0 = __floats2bfloat162_rn(v0, v1);
                __nv_bfloat162 o1 = __floats2bfloat162_rn(v2, v3);
                *(__nv_bfloat162*)&C[(size_t)r * ldc + c]       = o0;
                *(__nv_bfloat162*)&C[(size_t)(r + 8) * ldc + c] = o1;
            } else {
                float* C = (float*)Cv;
                float2 o0 = {v0, v1}, o1 = {v2, v3};
                *(float2*)&C[(size_t)r * ldc + c]       = o0;
                *(float2*)&C[(size_t)(r + 8) * ldc + c] = o1;
            }
        }
    }
}

// ================= conversion / split kernels ================================
__global__ __launch_bounds__(256) void k_split_expr(const float* __restrict__ X,
    __nv_bfloat16* __restrict__ hi, __nv_bfloat16* __restrict__ lo)
{
    const size_t idx4 = (size_t)blockIdx.x * 256 + threadIdx.x;
    if (idx4 >= (size_t)NPAD * (KPAD1 / 4)) return;
    const int j  = (int)(idx4 / (KPAD1 / 4));
    const int k0 = (int)(idx4 % (KPAD1 / 4)) * 4;
    __nv_bfloat16 h[4], l[4];
    #pragma unroll
    for (int i = 0; i < 4; i++) {
        const int k = k0 + i;
        const float v = (j < NREF && k < GENES) ? X[(size_t)j * GENES + k] : 0.0f;
        split2(v, h[i], l[i]);
    }
    *(uint2*)(hi + (size_t)j * KPAD1 + k0) = *(const uint2*)h;
    *(uint2*)(lo + (size_t)j * KPAD1 + k0) = *(const uint2*)l;
}

// transpose+split W[K,N] -> out[N, KP] K-major
__global__ __launch_bounds__(256) void k_split_wt(const float* __restrict__ W,
    __nv_bfloat16* __restrict__ hi, __nv_bfloat16* __restrict__ lo, int Kreal, int KP)
{
    const long long idx = (long long)blockIdx.x * 256 + threadIdx.x;
    if (idx >= (long long)DIM * KP) return;
    const int n = (int)(idx / KP);
    const int k = (int)(idx % KP);
    const float v = (k < Kreal) ? W[(size_t)k * DIM + n] : 0.0f;
    __nv_bfloat16 h, l;
    split2(v, h, l);
    hi[idx] = h; lo[idx] = l;
}

__global__ __launch_bounds__(256) void k_gelu_split(const float* __restrict__ P,
    __nv_bfloat16* __restrict__ hi, __nv_bfloat16* __restrict__ lo)
{
    const size_t idx = (size_t)blockIdx.x * 256 + threadIdx.x;
    if (idx >= (size_t)NPAD * DIM) return;
    __nv_bfloat16 h, l;
    split2(gelu_exact(P[idx]), h, l);
    hi[idx] = h; lo[idx] = l;
}

__global__ __launch_bounds__(256) void k_split_q(const float* __restrict__ q,
    __nv_bfloat16* __restrict__ hi)
{
    const size_t idx = (size_t)blockIdx.x * 256 + threadIdx.x;
    if (idx >= (size_t)NQ * DIM) return;
    hi[idx] = __float2bfloat16(q[idx]);
}

// --------- LayerNorm (in place) + 1/||row|| + fused bf16 normalized copy ----
__global__ __launch_bounds__(128) void k_ln(
    float* __restrict__ h, const float* __restrict__ gamma,
    const float* __restrict__ beta, float* __restrict__ rnorm,
    __nv_bfloat16* __restrict__ embn)
{
    const int row = blockIdx.x;
    const int tid = threadIdx.x;
    if (row >= NREF) {                          // padded rows: zero embn only
        uint2 z = {0u, 0u};
        ((uint2*)(embn + (size_t)row * DIM))[tid] = z;
        return;
    }
    const int lane = tid & 31, warp = tid >> 5;
    __shared__ float red[4];

    float4 v = ((const float4*)(h + (size_t)row * DIM))[tid];
    float s = v.x + v.y + v.z + v.w;
    #pragma unroll
    for (int o = 16; o; o >>= 1) s += __shfl_xor_sync(0xFFFFFFFFu, s, o);
    if (lane == 0) red[warp] = s;
    __syncthreads();
    const float mu = (red[0] + red[1] + red[2] + red[3]) * (1.0f / DIM);
    __syncthreads();
    float dx = v.x - mu, dy = v.y - mu, dz = v.z - mu, dw = v.w - mu;
    float s2 = dx*dx + dy*dy + dz*dz + dw*dw;
    #pragma unroll
    for (int o = 16; o; o >>= 1) s2 += __shfl_xor_sync(0xFFFFFFFFu, s2, o);
    if (lane == 0) red[warp] = s2;
    __syncthreads();
    const float var = (red[0] + red[1] + red[2] + red[3]) * (1.0f / DIM);
    __syncthreads();
    const float rs = rsqrtf(var + LN_EPS);
    const int c = tid * 4;
    float4 y;
    y.x = dx * rs * gamma[c + 0] + beta[c + 0];
    y.y = dy * rs * gamma[c + 1] + beta[c + 1];
    y.z = dz * rs * gamma[c + 2] + beta[c + 2];
    y.w = dw * rs * gamma[c + 3] + beta[c + 3];
    float n2 = y.x*y.x + y.y*y.y + y.z*y.z + y.w*y.w;
    #pragma unroll
    for (int o = 16; o; o >>= 1) n2 += __shfl_xor_sync(0xFFFFFFFFu, n2, o);
    if (lane == 0) red[warp] = n2;
    __syncthreads();
    const float rn = rsqrtf(red[0] + red[1] + red[2] + red[3]);
    if (tid == 0) rnorm[row] = rn;
    ((float4*)(h + (size_t)row * DIM))[tid] = y;
    __nv_bfloat162 e0 = __floats2bfloat162_rn(y.x * rn, y.y * rn);
    __nv_bfloat162 e1 = __floats2bfloat162_rn(y.z * rn, y.w * rn);
    *(__nv_bfloat162*)(embn + (size_t)row * DIM + c)     = e0;
    *(__nv_bfloat162*)(embn + (size_t)row * DIM + c + 2) = e1;
}

// ---------------- top-50: 2 global passes (bf16 keys) + smem radix refine ---
__device__ __forceinline__ unsigned f2key(float v) {
    unsigned u = __float_as_uint(v);
    return (u & 0x80000000u) ? ~u : (u | 0x80000000u);   // monotone increasing
}

#define TKBINS   2048
#define CAND_CAP 4096
__global__ __launch_bounds__(256) void k_topk(
    const __nv_bfloat16* __restrict__ sim, int* __restrict__ out_idx)
{
    const int q = blockIdx.x;
    const int tid = threadIdx.x;
    const __nv_bfloat16* __restrict__ row = sim + (size_t)q * NPAD;

    __shared__ unsigned hist[TKBINS];
    __shared__ unsigned csum[256];
    __shared__ unsigned ckey[CAND_CAP];
    __shared__ int      cidx[CAND_CAP];
    __shared__ int sh_bin, cnt, sh_want, cnt2;
    __shared__ unsigned sh_prefix;

    for (int i = tid; i < TKBINS; i += 256) hist[i] = 0;
    __syncthreads();
    for (int j = tid; j < NREF; j += 256)
        atomicAdd(&hist[f2key(__bfloat162float(row[j])) >> 21], 1u);
    __syncthreads();
    unsigned s = 0;
    #pragma unroll
    for (int b = 0; b < 8; b++) s += hist[tid * 8 + b];
    csum[tid] = s;
    __syncthreads();
    if (tid == 0) {
        unsigned cum = 0; int chunk = 255;
        for (; chunk > 0; chunk--) { if (cum + csum[chunk] >= TOPK) break; cum += csum[chunk]; }
        int b = chunk * 8 + 7;
        unsigned c2 = cum;
        for (; b > chunk * 8; b--) { if (c2 + hist[b] >= TOPK) break; c2 += hist[b]; }
        sh_bin = b;
        cnt = 0;
    }
    __syncthreads();
    const unsigned binT = (unsigned)sh_bin;

    for (int j = tid; j < NREF; j += 256) {
        const unsigned k = f2key(__bfloat162float(row[j]));
        if ((k >> 21) >= binT) {
            const int p = atomicAdd(&cnt, 1);
            if (p < CAND_CAP) { ckey[p] = k; cidx[p] = j; }
        }
    }
    __syncthreads();
    const int L = min(cnt, CAND_CAP);

    unsigned prefix = 0; int want = TOPK;
    #pragma unroll 1
    for (int p = 3; p >= 0; --p) {
        __syncthreads();
        if (tid < 256) hist[tid] = 0;
        __syncthreads();
        for (int i = tid; i < L; i += 256) {
            const unsigned k = ckey[i];
            if (p == 3 || (k >> ((p + 1) * 8)) == prefix)
                atomicAdd(&hist[(k >> (p * 8)) & 255u], 1u);
        }
        __syncthreads();
        if (tid == 0) {
            unsigned cum = 0;
            for (int b = 255; b >= 0; --b) {
                cum += hist[b];
                if ((int)cum >= want) {
                    sh_want = want - (int)(cum - hist[b]);
                    sh_prefix = (prefix << 8) | (unsigned)b;
                    break;
                }
            }
            cnt2 = 0;
        }
        __syncthreads();
        prefix = sh_prefix;
        want = sh_want;
    }
    const unsigned T = prefix;

    for (int i = tid; i < L; i += 256) {
        if (ckey[i] > T) {
            const int p = atomicAdd(&cnt2, 1);
            if (p < TOPK) out_idx[q * TOPK + p] = cidx[i];
        }
    }
    __syncthreads();
    for (int i = tid; i < L; i += 256) {
        if (ckey[i] == T) {
            const int p = atomicAdd(&cnt2, 1);
            if (p < TOPK) out_idx[q * TOPK + p] = cidx[i];
        }
    }
}

// ---------------- distances + weights + weighted expression mean ------------
__global__ __launch_bounds__(256) void k_predict(
    const float* __restrict__ qf, const float* __restrict__ expr,
    const float* __restrict__ emb, const int* __restrict__ idx,
    float* __restrict__ out)
{
    const int q = blockIdx.x;
    const int tid = threadIdx.x;
    const int lane = tid & 31, warp = tid >> 5;

    __shared__ float sq[DIM];
    __shared__ int   sidx[TOPK];
    __shared__ float swt[TOPK];
    __shared__ float s_invw;

    for (int c = tid; c < DIM; c += 256) sq[c] = qf[(size_t)q * DIM + c];
    if (tid < TOPK) sidx[tid] = idx[q * TOPK + tid];
    __syncthreads();

    for (int k = warp; k < TOPK; k += 8) {
        const float* __restrict__ e = emb + (size_t)sidx[k] * DIM;
        float s = 0.0f;
        for (int c = lane; c < DIM; c += 32) {
            const float d = e[c] - sq[c];
            s = fmaf(d, d, s);
        }
        #pragma unroll
        for (int o = 16; o; o >>= 1) s += __shfl_xor_sync(0xFFFFFFFFu, s, o);
        if (lane == 0) swt[k] = s;
    }
    __syncthreads();

    if (tid == 0) {
        // anchor at min distance: pred is exactly invariant to anchor choice
        float a = swt[0];
        for (int k = 1; k < TOPK; k++) a = fminf(a, swt[k]);
        float sw = 0.0f;
        for (int k = 0; k < TOPK; k++) {
            const float w = expf(-(swt[k] - a + 1.0f));
            swt[k] = w;
            sw += w;
        }
        s_invw = 1.0f / sw;
    }
    __syncthreads();

    const float inv = s_invw;
    for (int g = tid; g < GENES; g += 256) {
        float acc = 0.0f;
        #pragma unroll 10
        for (int k = 0; k < TOPK; k++)
            acc = fmaf(swt[k], expr[(size_t)sidx[k] * GENES + g], acc);
        out[(size_t)q * GENES + g] = acc * inv;
    }
}

// ---------------- launch ----------------------------------------------------
extern "C" void kernel_launch(void* const* d_in, const int* in_sizes, int n_in,
                              void* d_out, int out_size)
{
    const float* imgf  = (const float*)d_in[0];
    const float* expr  = (const float*)d_in[1];
    const float* W1    = (const float*)d_in[2];
    const float* b1    = (const float*)d_in[3];
    const float* W2    = (const float*)d_in[4];
    const float* b2    = (const float*)d_in[5];
    const float* gamma = (const float*)d_in[6];
    const float* beta  = (const float*)d_in[7];
    float* out = (float*)d_out;

    __nv_bfloat16 *eh, *el, *w1h, *w1l, *w2h, *w2l, *gh, *gl, *embn, *qh, *sim;
    float *proj, *emb, *rnorm;
    int *idxp;
    cudaGetSymbolAddress((void**)&eh,   g_expr_hi);
    cudaGetSymbolAddress((void**)&el,   g_expr_lo);
    cudaGetSymbolAddress((void**)&w1h,  g_w1t_hi);
    cudaGetSymbolAddress((void**)&w1l,  g_w1t_lo);
    cudaGetSymbolAddress((void**)&w2h,  g_w2t_hi);
    cudaGetSymbolAddress((void**)&w2l,  g_w2t_lo);
    cudaGetSymbolAddress((void**)&gh,   g_g_hi);
    cudaGetSymbolAddress((void**)&gl,   g_g_lo);
    cudaGetSymbolAddress((void**)&embn, g_embn);
    cudaGetSymbolAddress((void**)&qh,   g_qhi);
    cudaGetSymbolAddress((void**)&sim,  g_sim);
    cudaGetSymbolAddress((void**)&proj, g_proj);
    cudaGetSymbolAddress((void**)&emb,  g_emb);
    cudaGetSymbolAddress((void**)&rnorm,g_rnorm);
    cudaGetSymbolAddress((void**)&idxp, g_idx);

    const int SM3 = 2 * 4 * TILE_B;   // 81920 B -> 2 CTAs/SM (proven)
    const int SM1 = 2 * 2 * TILE_B;   // 40960 B
    cudaFuncSetAttribute(k_mma_gemm<3,0,2>, cudaFuncAttributeMaxDynamicSharedMemorySize, SM3);
    cudaFuncSetAttribute(k_mma_gemm<3,1,2>, cudaFuncAttributeMaxDynamicSharedMemorySize, SM3);
    cudaFuncSetAttribute(k_mma_gemm<1,3,0>, cudaFuncAttributeMaxDynamicSharedMemorySize, SM1);

    // 0) splits / conversions (proven coalesced split kernels)
    k_split_expr<<<(unsigned)(((size_t)NPAD * (KPAD1/4) + 255) / 256), 256>>>(expr, eh, el);
    k_split_wt<<<(unsigned)(((size_t)DIM * KPAD1 + 255) / 256), 256>>>(W1, w1h, w1l, GENES, KPAD1);
    k_split_wt<<<(unsigned)(((size_t)DIM * DIM + 255) / 256), 256>>>(W2, w2h, w2l, DIM, DIM);
    k_split_q<<<(unsigned)(((size_t)NQ * DIM + 255) / 256), 256>>>(imgf, qh);

    // 1) proj = expr @ W1 + b1
    //    serpentine pairs: grid (1568, 2); consecutive bids share an A row-tile
    k_mma_gemm<3,0,2><<<dim3(2 * NPAD / 128, DIM / 256), 256, SM3>>>(
        eh, el, w1h, w1l, b1, nullptr, proj, KPAD1, DIM);

    // 2) gelu(proj) split
    k_gelu_split<<<(unsigned)(((size_t)NPAD * DIM + 255) / 256), 256>>>(proj, gh, gl);

    // 3) emb = gelu(proj) @ W2 + b2 + proj   (same serpentine pairing)
    k_mma_gemm<3,1,2><<<dim3(2 * NPAD / 128, DIM / 256), 256, SM3>>>(
        gh, gl, w2h, w2l, b2, proj, emb, DIM, DIM);

    // 4) LayerNorm in place + 1/||row|| + fused bf16 normalized emb
    k_ln<<<NPAD, 128>>>(emb, gamma, beta, rnorm, embn);

    // 5) sim = q @ embn^T  (1-term bf16, bf16 keys out; plain proven grid)
    k_mma_gemm<1,3,0><<<dim3(NQ / 128, NPAD / 128), 256, SM1>>>(
        qh, qh, embn, embn, nullptr, nullptr, sim, DIM, NPAD);

    // 6) exact top-50 set per query (on bf16 keys)
    k_topk<<<NQ, 256>>>(sim, idxp);

    // 7) distances -> weights -> weighted gene means
    k_predict<<<NQ, 256>>>(imgf, expr, emb, idxp, out);
}

// round 15
// speedup vs baseline: 1.1484x; 1.0354x over previous
#include <cuda_runtime.h>
#include <cuda_bf16.h>
#include <math.h>
#include <stdint.h>

#define NQ    2048
#define NREF  100000
#define GENES 3467
#define DIM   512
#define TOPK  50
#define LN_EPS 1e-5f

#define KPAD1 3520          // GENES padded to mult of 32
#define NPAD  100352        // NREF padded to mult of 128
#define RS    40            // smem row stride in bf16 (80B, conflict-free ldmatrix)

// ---------------- scratch (device globals; no allocation allowed) ----------
__device__ __nv_bfloat16 g_w1t_hi[(size_t)DIM * KPAD1];
__device__ __nv_bfloat16 g_w1t_lo[(size_t)DIM * KPAD1];
__device__ __nv_bfloat16 g_w2t_hi[(size_t)DIM * DIM];
__device__ __nv_bfloat16 g_w2t_lo[(size_t)DIM * DIM];
__device__ __nv_bfloat16 g_g_hi[(size_t)NPAD * DIM];
__device__ __nv_bfloat16 g_g_lo[(size_t)NPAD * DIM];
__device__ __nv_bfloat16 g_embn[(size_t)NPAD * DIM];
__device__ __nv_bfloat16 g_qhi[(size_t)NQ * DIM];
__device__ float g_proj[(size_t)NPAD * DIM];
__device__ float g_emb [(size_t)NPAD * DIM];
__device__ float g_rnorm[NREF];
__device__ __nv_bfloat16 g_sim [(size_t)NQ * NPAD];   // bf16 ranking keys
__device__ int   g_idx [NQ * TOPK];

// ---------------- PTX helpers (base compute_103 features only) --------------
__device__ __forceinline__ uint32_t smem_u32(const void* p) {
    uint32_t a;
    asm("{ .reg .u64 t; cvta.to.shared.u64 t, %1; cvt.u32.u64 %0, t; }" : "=r"(a) : "l"(p));
    return a;
}
__device__ __forceinline__ void cp16(uint32_t sa, const void* ga) {
    asm volatile("cp.async.cg.shared.global [%0], [%1], 16;" :: "r"(sa), "l"(ga));
}
#define CP_COMMIT() asm volatile("cp.async.commit_group;" ::: "memory")
#define CP_WAIT(n)  asm volatile("cp.async.wait_group %0;" :: "n"(n) : "memory")

__device__ __forceinline__ void ldm_x4(uint32_t* r, uint32_t addr) {
    asm volatile("ldmatrix.sync.aligned.m8n8.x4.shared.b16 {%0,%1,%2,%3}, [%4];"
        : "=r"(r[0]), "=r"(r[1]), "=r"(r[2]), "=r"(r[3]) : "r"(addr));
}
__device__ __forceinline__ void mma16816(float* d, const uint32_t* a, const uint32_t* b) {
    asm volatile(
        "mma.sync.aligned.m16n8k16.row.col.f32.bf16.bf16.f32 "
        "{%0,%1,%2,%3}, {%4,%5,%6,%7}, {%8,%9}, {%0,%1,%2,%3};"
        : "+f"(d[0]), "+f"(d[1]), "+f"(d[2]), "+f"(d[3])
        : "r"(a[0]), "r"(a[1]), "r"(a[2]), "r"(a[3]), "r"(b[0]), "r"(b[1]));
}

// ---------------- bf16 split helpers ----------------------------------------
__device__ __forceinline__ void split2(float x, __nv_bfloat16& h, __nv_bfloat16& l) {
    h = __float2bfloat16(x);
    l = __float2bfloat16(x - __bfloat162float(h));
}
__device__ __forceinline__ float gelu_exact(float x) {
    return 0.5f * x * (1.0f + erff(x * 0.70710678118654752f));
}

#define TILE_B (128 * RS * 2)   // 10240 bytes per tile

// ---- shared compute core: one BK=32 block, 3-term or 1-term -----------------
template<int TERMS>
__device__ __forceinline__ void compute_block(
    float acc[4][4][4], uint32_t sbase, int wm, int wn, int lane)
{
    const uint32_t saHI = sbase;
    const uint32_t saLO = sbase + TILE_B;
    const uint32_t sbHI = sbase + ((TERMS == 3) ? 2 : 1) * TILE_B;
    const uint32_t sbLO = sbase + 3 * TILE_B;
    #pragma unroll
    for (int ks = 0; ks < 2; ks++) {
        const int ko = ks * 16;
        const uint32_t aoff = (uint32_t)((wm + (lane & 15)) * RS + ko + (lane >> 4) * 8) * 2;
        const uint32_t boff = (uint32_t)((wn + ((lane >> 4) & 1) * 8 + (lane & 7)) * RS
                                         + ko + ((lane >> 3) & 1) * 8) * 2;
        uint32_t af[4][4], bf[2][4];
        #pragma unroll
        for (int i = 0; i < 4; i++) ldm_x4(af[i], saHI + aoff + i * 16 * RS * 2);
        #pragma unroll
        for (int p = 0; p < 2; p++) ldm_x4(bf[p], sbHI + boff + p * 16 * RS * 2);
        #pragma unroll
        for (int i = 0; i < 4; i++)
            #pragma unroll
            for (int j = 0; j < 4; j++)
                mma16816(acc[i][j], af[i], &bf[j >> 1][(j & 1) * 2]);
        if (TERMS == 3) {
            uint32_t bl[2][4];
            #pragma unroll
            for (int p = 0; p < 2; p++) ldm_x4(bl[p], sbLO + boff + p * 16 * RS * 2);
            #pragma unroll
            for (int i = 0; i < 4; i++)
                #pragma unroll
                for (int j = 0; j < 4; j++)
                    mma16816(acc[i][j], af[i], &bl[j >> 1][(j & 1) * 2]);
            #pragma unroll
            for (int i = 0; i < 4; i++) ldm_x4(af[i], saLO + aoff + i * 16 * RS * 2);
            #pragma unroll
            for (int i = 0; i < 4; i++)
                #pragma unroll
                for (int j = 0; j < 4; j++)
                    mma16816(acc[i][j], af[i], &bf[j >> 1][(j & 1) * 2]);
        }
    }
}

// ================= generic HMMA GEMM (R10-champion mainloop) =================
// C[M,N] = Ahl[M,K] @ Bhl[N,K]^T.  TERMS: 1 or 3.
// EPI: 0=f32+bias, 1=f32+bias+resid, 3=bf16 raw.  Grid: x=row, y=col (proven).
template<int TERMS, int EPI>
__global__ __launch_bounds__(256) void k_mma_gemm(
    const __nv_bfloat16* __restrict__ Ahi, const __nv_bfloat16* __restrict__ Alo,
    const __nv_bfloat16* __restrict__ Bhi, const __nv_bfloat16* __restrict__ Blo,
    const float* __restrict__ bias, const float* __restrict__ resid,
    void* __restrict__ Cv, int K, int ldc)
{
    extern __shared__ char smem[];
    constexpr int NTILES = (TERMS == 3) ? 4 : 2;
    constexpr int STAGE  = TILE_B * NTILES;
    const uint32_t sb = smem_u32(smem);
    const int tid = threadIdx.x, wid = tid >> 5, lane = tid & 31;
    const int row0 = blockIdx.x * 128;
    const int col0 = blockIdx.y * 128;
    const int wm = (wid >> 2) * 64, wn = (wid & 3) * 32;

    float acc[4][4][4] = {};
    const int NKB = K / 32;

    auto load_stage = [&](int s, int kb) {
        const int kpos = kb * 32;
        const uint32_t sbase = sb + s * STAGE;
        #pragma unroll
        for (int i = 0; i < 2; i++) {
            const int idx = tid + i * 256;
            const int r = idx >> 2, c = idx & 3;
            const uint32_t so = r * (RS * 2) + c * 16;
            const size_t gA = (size_t)(row0 + r) * K + kpos + c * 8;
            const size_t gB = (size_t)(col0 + r) * K + kpos + c * 8;
            cp16(sbase + 0 * TILE_B + so, Ahi + gA);
            if (TERMS == 3) {
                cp16(sbase + 1 * TILE_B + so, Alo + gA);
                cp16(sbase + 2 * TILE_B + so, Bhi + gB);
                cp16(sbase + 3 * TILE_B + so, Blo + gB);
            } else {
                cp16(sbase + 1 * TILE_B + so, Bhi + gB);
            }
        }
    };

    load_stage(0, 0); CP_COMMIT();

    for (int kb = 0; kb < NKB; kb++) {
        const int s = kb & 1;
        if (kb + 1 < NKB) { load_stage(s ^ 1, kb + 1); CP_COMMIT(); CP_WAIT(1); }
        else              { CP_WAIT(0); }
        __syncthreads();
        compute_block<TERMS>(acc, sb + s * STAGE, wm, wn, lane);
        __syncthreads();
    }

    // ---- epilogue --------------------------------------------------------
    const int g  = lane >> 2;
    const int tg = (lane & 3) * 2;
    #pragma unroll
    for (int i = 0; i < 4; i++) {
        #pragma unroll
        for (int j = 0; j < 4; j++) {
            const int r = row0 + wm + i * 16 + g;
            const int c = col0 + wn + j * 8 + tg;
            float v0 = acc[i][j][0], v1 = acc[i][j][1];
            float v2 = acc[i][j][2], v3 = acc[i][j][3];
            if (EPI == 0 || EPI == 1) {
                const float b0 = bias[c], b1 = bias[c + 1];
                v0 += b0; v1 += b1; v2 += b0; v3 += b1;
            }
            if (EPI == 1) {
                const float2 r0 = *(const float2*)&resid[(size_t)r * ldc + c];
                const float2 r1 = *(const float2*)&resid[(size_t)(r + 8) * ldc + c];
                v0 += r0.x; v1 += r0.y; v2 += r1.x; v3 += r1.y;
            }
            if (EPI == 3) {
                __nv_bfloat16* C = (__nv_bfloat16*)Cv;
                __nv_bfloat162 o0 = __floats2bfloat162_rn(v0, v1);
                __nv_bfloat162 o1 = __floats2bfloat162_rn(v2, v3);
                *(__nv_bfloat162*)&C[(size_t)r * ldc + c]       = o0;
                *(__nv_bfloat162*)&C[(size_t)(r + 8) * ldc + c] = o1;
            } else {
                float* C = (float*)Cv;
                float2 o0 = {v0, v1}, o1 = {v2, v3};
                *(float2*)&C[(size_t)r * ldc + c]       = o0;
                *(float2*)&C[(size_t)(r + 8) * ldc + c] = o1;
            }
        }
    }
}

// ========== GEMM1 fused v2: A f32 -> (hi,lo) conversion inside loader ========
// proj[NPAD,DIM] = expr[NREF,GENES](f32) @ W1t[DIM,KPAD1]^T + b1
// Fixes vs R11: (1) chunk geometry r=idx>>3 keeps each warp within 4 rows
// (coalesced, L1 absorbs scalar re-touches); (2) B keeps champion early-issue
// CP_WAIT(1) pipeline; (3) A(kb+1) STS'd alongside loadB(kb+1) -> 2 syncs/iter.
__global__ __launch_bounds__(256, 2) void k_gemm1_fused(
    const float* __restrict__ expr,
    const __nv_bfloat16* __restrict__ Bhi, const __nv_bfloat16* __restrict__ Blo,
    const float* __restrict__ bias, float* __restrict__ C)
{
    extern __shared__ char smem[];
    constexpr int STAGE = TILE_B * 4;         // Ahi, Alo, Bhi, Blo
    const uint32_t sb = smem_u32(smem);
    const int tid = threadIdx.x, wid = tid >> 5, lane = tid & 31;
    const int row0 = blockIdx.x * 128;        // proven unswapped grid
    const int col0 = blockIdx.y * 128;
    const int wm = (wid >> 2) * 64, wn = (wid & 3) * 32;

    float acc[4][4][4] = {};
    const int NKB = KPAD1 / 32;               // 110

    // A chunk geometry: 1024 chunks of 4 f32; thread does 4 chunks.
    // chunk idx -> row r = idx>>3 (warp spans 4 rows), col group c4 = idx&7.
    auto ldgA = [&](int kb, float* v) {
        const int kpos = kb * 32;
        #pragma unroll
        for (int i = 0; i < 4; i++) {
            const int idx = tid + i * 256;
            const int r = idx >> 3, c4 = idx & 7;
            const int grow = row0 + r;
            const bool rowok = grow < NREF;
            const float* __restrict__ p = expr + (size_t)grow * GENES + kpos + c4 * 4;
            #pragma unroll
            for (int k = 0; k < 4; k++) {
                const int cg = kpos + c4 * 4 + k;
                v[i * 4 + k] = (rowok && cg < GENES) ? __ldg(p + k) : 0.0f;
            }
        }
    };
    auto stsA = [&](int s, const float* v) {
        #pragma unroll
        for (int i = 0; i < 4; i++) {
            const int idx = tid + i * 256;
            const int r = idx >> 3, c4 = idx & 7;
            __align__(8) __nv_bfloat16 h[4], l[4];
            #pragma unroll
            for (int k = 0; k < 4; k++) split2(v[i * 4 + k], h[k], l[k]);
            const uint32_t so = (uint32_t)(r * (RS * 2) + c4 * 8);
            const uint32_t off = s * STAGE;
            *(uint2*)(smem + off + 0 * TILE_B + so) = *(const uint2*)h;
            *(uint2*)(smem + off + 1 * TILE_B + so) = *(const uint2*)l;
        }
    };
    auto loadB = [&](int s, int kb) {
        const int kpos = kb * 32;
        const uint32_t sbase = sb + s * STAGE;
        #pragma unroll
        for (int i = 0; i < 2; i++) {
            const int idx = tid + i * 256;
            const int r = idx >> 2, c = idx & 3;
            const uint32_t so = r * (RS * 2) + c * 16;
            const size_t gB = (size_t)(col0 + r) * KPAD1 + kpos + c * 8;
            cp16(sbase + 2 * TILE_B + so, Bhi + gB);
            cp16(sbase + 3 * TILE_B + so, Blo + gB);
        }
    };

    float av[16];
    // prologue: A(0) -> stage0, B(0) in flight, A(1) -> regs
    ldgA(0, av);
    loadB(0, 0); CP_COMMIT();          // group0 = B(0)
    stsA(0, av);                       // no one computing yet
    ldgA(1, av);

    for (int kb = 0; kb < NKB; kb++) {
        const int s = kb & 1;
        if (kb + 1 < NKB) {
            loadB(s ^ 1, kb + 1);      // early-issue B(kb+1) (champion pattern)
            stsA(s ^ 1, av);           // A(kb+1) -> stage s^1 (disjoint from B cp.async region)
            CP_COMMIT();
            CP_WAIT(1);                // B(kb) landed
            if (kb + 2 < NKB) ldgA(kb + 2, av);   // hidden under compute(kb)
        } else {
            CP_WAIT(0);
        }
        __syncthreads();               // B(kb)+A(kb) visible; compute(kb-1) done
        compute_block<3>(acc, sb + s * STAGE, wm, wn, lane);
        __syncthreads();               // stage s free for iter kb+1 writes
    }

    // epilogue: f32 + bias
    const int g  = lane >> 2;
    const int tg = (lane & 3) * 2;
    #pragma unroll
    for (int i = 0; i < 4; i++) {
        #pragma unroll
        for (int j = 0; j < 4; j++) {
            const int r = row0 + wm + i * 16 + g;
            const int c = col0 + wn + j * 8 + tg;
            const float b0 = bias[c], b1 = bias[c + 1];
            float2 o0 = {acc[i][j][0] + b0, acc[i][j][1] + b1};
            float2 o1 = {acc[i][j][2] + b0, acc[i][j][3] + b1};
            *(float2*)&C[(size_t)r * DIM + c]       = o0;
            *(float2*)&C[(size_t)(r + 8) * DIM + c] = o1;
        }
    }
}

// ================= conversion / split kernels ================================
// transpose+split W[K,N] -> out[N, KP] K-major
__global__ __launch_bounds__(256) void k_split_wt(const float* __restrict__ W,
    __nv_bfloat16* __restrict__ hi, __nv_bfloat16* __restrict__ lo, int Kreal, int KP)
{
    const long long idx = (long long)blockIdx.x * 256 + threadIdx.x;
    if (idx >= (long long)DIM * KP) return;
    const int n = (int)(idx / KP);
    const int k = (int)(idx % KP);
    const float v = (k < Kreal) ? W[(size_t)k * DIM + n] : 0.0f;
    __nv_bfloat16 h, l;
    split2(v, h, l);
    hi[idx] = h; lo[idx] = l;
}

__global__ __launch_bounds__(256) void k_gelu_split(const float* __restrict__ P,
    __nv_bfloat16* __restrict__ hi, __nv_bfloat16* __restrict__ lo)
{
    const size_t idx = (size_t)blockIdx.x * 256 + threadIdx.x;
    if (idx >= (size_t)NPAD * DIM) return;
    __nv_bfloat16 h, l;
    split2(gelu_exact(P[idx]), h, l);
    hi[idx] = h; lo[idx] = l;
}

__global__ __launch_bounds__(256) void k_split_q(const float* __restrict__ q,
    __nv_bfloat16* __restrict__ hi)
{
    const size_t idx = (size_t)blockIdx.x * 256 + threadIdx.x;
    if (idx >= (size_t)NQ * DIM) return;
    hi[idx] = __float2bfloat16(q[idx]);
}

// --------- LayerNorm (in place) + 1/||row|| + fused bf16 normalized copy ----
__global__ __launch_bounds__(128) void k_ln(
    float* __restrict__ h, const float* __restrict__ gamma,
    const float* __restrict__ beta, float* __restrict__ rnorm,
    __nv_bfloat16* __restrict__ embn)
{
    const int row = blockIdx.x;
    const int tid = threadIdx.x;
    if (row >= NREF) {                          // padded rows: zero embn only
        uint2 z = {0u, 0u};
        ((uint2*)(embn + (size_t)row * DIM))[tid] = z;
        return;
    }
    const int lane = tid & 31, warp = tid >> 5;
    __shared__ float red[4];

    float4 v = ((const float4*)(h + (size_t)row * DIM))[tid];
    float s = v.x + v.y + v.z + v.w;
    #pragma unroll
    for (int o = 16; o; o >>= 1) s += __shfl_xor_sync(0xFFFFFFFFu, s, o);
    if (lane == 0) red[warp] = s;
    __syncthreads();
    const float mu = (red[0] + red[1] + red[2] + red[3]) * (1.0f / DIM);
    __syncthreads();
    float dx = v.x - mu, dy = v.y - mu, dz = v.z - mu, dw = v.w - mu;
    float s2 = dx*dx + dy*dy + dz*dz + dw*dw;
    #pragma unroll
    for (int o = 16; o; o >>= 1) s2 += __shfl_xor_sync(0xFFFFFFFFu, s2, o);
    if (lane == 0) red[warp] = s2;
    __syncthreads();
    const float var = (red[0] + red[1] + red[2] + red[3]) * (1.0f / DIM);
    __syncthreads();
    const float rs = rsqrtf(var + LN_EPS);
    const int c = tid * 4;
    float4 y;
    y.x = dx * rs * gamma[c + 0] + beta[c + 0];
    y.y = dy * rs * gamma[c + 1] + beta[c + 1];
    y.z = dz * rs * gamma[c + 2] + beta[c + 2];
    y.w = dw * rs * gamma[c + 3] + beta[c + 3];
    float n2 = y.x*y.x + y.y*y.y + y.z*y.z + y.w*y.w;
    #pragma unroll
    for (int o = 16; o; o >>= 1) n2 += __shfl_xor_sync(0xFFFFFFFFu, n2, o);
    if (lane == 0) red[warp] = n2;
    __syncthreads();
    const float rn = rsqrtf(red[0] + red[1] + red[2] + red[3]);
    if (tid == 0) rnorm[row] = rn;
    ((float4*)(h + (size_t)row * DIM))[tid] = y;
    __nv_bfloat162 e0 = __floats2bfloat162_rn(y.x * rn, y.y * rn);
    __nv_bfloat162 e1 = __floats2bfloat162_rn(y.z * rn, y.w * rn);
    *(__nv_bfloat162*)(embn + (size_t)row * DIM + c)     = e0;
    *(__nv_bfloat162*)(embn + (size_t)row * DIM + c + 2) = e1;
}

// ---------------- top-50: 2 global passes (bf16 keys) + smem radix refine ---
__device__ __forceinline__ unsigned f2key(float v) {
    unsigned u = __float_as_uint(v);
    return (u & 0x80000000u) ? ~u : (u | 0x80000000u);   // monotone increasing
}

#define TKBINS   2048
#define CAND_CAP 4096
__global__ __launch_bounds__(256) void k_topk(
    const __nv_bfloat16* __restrict__ sim, int* __restrict__ out_idx)
{
    const int q = blockIdx.x;
    const int tid = threadIdx.x;
    const __nv_bfloat16* __restrict__ row = sim + (size_t)q * NPAD;

    __shared__ unsigned hist[TKBINS];
    __shared__ unsigned csum[256];
    __shared__ unsigned ckey[CAND_CAP];
    __shared__ int      cidx[CAND_CAP];
    __shared__ int sh_bin, cnt, sh_want, cnt2;
    __shared__ unsigned sh_prefix;

    for (int i = tid; i < TKBINS; i += 256) hist[i] = 0;
    __syncthreads();
    for (int j = tid; j < NREF; j += 256)
        atomicAdd(&hist[f2key(__bfloat162float(row[j])) >> 21], 1u);
    __syncthreads();
    unsigned s = 0;
    #pragma unroll
    for (int b = 0; b < 8; b++) s += hist[tid * 8 + b];
    csum[tid] = s;
    __syncthreads();
    if (tid == 0) {
        unsigned cum = 0; int chunk = 255;
        for (; chunk > 0; chunk--) { if (cum + csum[chunk] >= TOPK) break; cum += csum[chunk]; }
        int b = chunk * 8 + 7;
        unsigned c2 = cum;
        for (; b > chunk * 8; b--) { if (c2 + hist[b] >= TOPK) break; c2 += hist[b]; }
        sh_bin = b;
        cnt = 0;
    }
    __syncthreads();
    const unsigned binT = (unsigned)sh_bin;

    for (int j = tid; j < NREF; j += 256) {
        const unsigned k = f2key(__bfloat162float(row[j]));
        if ((k >> 21) >= binT) {
            const int p = atomicAdd(&cnt, 1);
            if (p < CAND_CAP) { ckey[p] = k; cidx[p] = j; }
        }
    }
    __syncthreads();
    const int L = min(cnt, CAND_CAP);

    unsigned prefix = 0; int want = TOPK;
    #pragma unroll 1
    for (int p = 3; p >= 0; --p) {
        __syncthreads();
        if (tid < 256) hist[tid] = 0;
        __syncthreads();
        for (int i = tid; i < L; i += 256) {
            const unsigned k = ckey[i];
            if (p == 3 || (k >> ((p + 1) * 8)) == prefix)
                atomicAdd(&hist[(k >> (p * 8)) & 255u], 1u);
        }
        __syncthreads();
        if (tid == 0) {
            unsigned cum = 0;
            for (int b = 255; b >= 0; --b) {
                cum += hist[b];
                if ((int)cum >= want) {
                    sh_want = want - (int)(cum - hist[b]);
                    sh_prefix = (prefix << 8) | (unsigned)b;
                    break;
                }
            }
            cnt2 = 0;
        }
        __syncthreads();
        prefix = sh_prefix;
        want = sh_want;
    }
    const unsigned T = prefix;

    for (int i = tid; i < L; i += 256) {
        if (ckey[i] > T) {
            const int p = atomicAdd(&cnt2, 1);
            if (p < TOPK) out_idx[q * TOPK + p] = cidx[i];
        }
    }
    __syncthreads();
    for (int i = tid; i < L; i += 256) {
        if (ckey[i] == T) {
            const int p = atomicAdd(&cnt2, 1);
            if (p < TOPK) out_idx[q * TOPK + p] = cidx[i];
        }
    }
}

// ---------------- distances + weights + weighted expression mean ------------
__global__ __launch_bounds__(256) void k_predict(
    const float* __restrict__ qf, const float* __restrict__ expr,
    const float* __restrict__ emb, const int* __restrict__ idx,
    float* __restrict__ out)
{
    const int q = blockIdx.x;
    const int tid = threadIdx.x;
    const int lane = tid & 31, warp = tid >> 5;

    __shared__ float sq[DIM];
    __shared__ int   sidx[TOPK];
    __shared__ float swt[TOPK];
    __shared__ float s_invw;

    for (int c = tid; c < DIM; c += 256) sq[c] = qf[(size_t)q * DIM + c];
    if (tid < TOPK) sidx[tid] = idx[q * TOPK + tid];
    __syncthreads();

    for (int k = warp; k < TOPK; k += 8) {
        const float* __restrict__ e = emb + (size_t)sidx[k] * DIM;
        float s = 0.0f;
        for (int c = lane; c < DIM; c += 32) {
            const float d = e[c] - sq[c];
            s = fmaf(d, d, s);
        }
        #pragma unroll
        for (int o = 16; o; o >>= 1) s += __shfl_xor_sync(0xFFFFFFFFu, s, o);
        if (lane == 0) swt[k] = s;
    }
    __syncthreads();

    if (tid == 0) {
        // anchor at min distance: pred is exactly invariant to anchor choice
        float a = swt[0];
        for (int k = 1; k < TOPK; k++) a = fminf(a, swt[k]);
        float sw = 0.0f;
        for (int k = 0; k < TOPK; k++) {
            const float w = expf(-(swt[k] - a + 1.0f));
            swt[k] = w;
            sw += w;
        }
        s_invw = 1.0f / sw;
    }
    __syncthreads();

    const float inv = s_invw;
    for (int g = tid; g < GENES; g += 256) {
        float acc = 0.0f;
        #pragma unroll 10
        for (int k = 0; k < TOPK; k++)
            acc = fmaf(swt[k], expr[(size_t)sidx[k] * GENES + g], acc);
        out[(size_t)q * GENES + g] = acc * inv;
    }
}

// ---------------- launch ----------------------------------------------------
extern "C" void kernel_launch(void* const* d_in, const int* in_sizes, int n_in,
                              void* d_out, int out_size)
{
    const float* imgf  = (const float*)d_in[0];
    const float* expr  = (const float*)d_in[1];
    const float* W1    = (const float*)d_in[2];
    const float* b1    = (const float*)d_in[3];
    const float* W2    = (const float*)d_in[4];
    const float* b2    = (const float*)d_in[5];
    const float* gamma = (const float*)d_in[6];
    const float* beta  = (const float*)d_in[7];
    float* out = (float*)d_out;

    __nv_bfloat16 *w1h, *w1l, *w2h, *w2l, *gh, *gl, *embn, *qh, *sim;
    float *proj, *emb, *rnorm;
    int *idxp;
    cudaGetSymbolAddress((void**)&w1h,  g_w1t_hi);
    cudaGetSymbolAddress((void**)&w1l,  g_w1t_lo);
    cudaGetSymbolAddress((void**)&w2h,  g_w2t_hi);
    cudaGetSymbolAddress((void**)&w2l,  g_w2t_lo);
    cudaGetSymbolAddress((void**)&gh,   g_g_hi);
    cudaGetSymbolAddress((void**)&gl,   g_g_lo);
    cudaGetSymbolAddress((void**)&embn, g_embn);
    cudaGetSymbolAddress((void**)&qh,   g_qhi);
    cudaGetSymbolAddress((void**)&sim,  g_sim);
    cudaGetSymbolAddress((void**)&proj, g_proj);
    cudaGetSymbolAddress((void**)&emb,  g_emb);
    cudaGetSymbolAddress((void**)&rnorm,g_rnorm);
    cudaGetSymbolAddress((void**)&idxp, g_idx);

    const int SM3 = 2 * 4 * TILE_B;   // 81920 B -> 2 CTAs/SM (proven)
    const int SM1 = 2 * 2 * TILE_B;   // 40960 B
    cudaFuncSetAttribute(k_gemm1_fused,   cudaFuncAttributeMaxDynamicSharedMemorySize, SM3);
    cudaFuncSetAttribute(k_mma_gemm<3,1>, cudaFuncAttributeMaxDynamicSharedMemorySize, SM3);
    cudaFuncSetAttribute(k_mma_gemm<1,3>, cudaFuncAttributeMaxDynamicSharedMemorySize, SM1);

    // 0) weight splits / q conversion (small)
    k_split_wt<<<(unsigned)(((size_t)DIM * KPAD1 + 255) / 256), 256>>>(W1, w1h, w1l, GENES, KPAD1);
    k_split_wt<<<(unsigned)(((size_t)DIM * DIM + 255) / 256), 256>>>(W2, w2h, w2l, DIM, DIM);
    k_split_q<<<(unsigned)(((size_t)NQ * DIM + 255) / 256), 256>>>(imgf, qh);

    // 1) proj = expr @ W1 + b1  (fused f32->hi/lo v2; champion grid + pipeline)
    k_gemm1_fused<<<dim3(NPAD / 128, DIM / 128), 256, SM3>>>(expr, w1h, w1l, b1, proj);

    // 2) gelu(proj) split
    k_gelu_split<<<(unsigned)(((size_t)NPAD * DIM + 255) / 256), 256>>>(proj, gh, gl);

    // 3) emb = gelu(proj) @ W2 + b2 + proj   (champion mainloop)
    k_mma_gemm<3,1><<<dim3(NPAD / 128, DIM / 128), 256, SM3>>>(
        gh, gl, w2h, w2l, b2, proj, emb, DIM, DIM);

    // 4) LayerNorm in place + 1/||row|| + fused bf16 normalized emb
    k_ln<<<NPAD, 128>>>(emb, gamma, beta, rnorm, embn);

    // 5) sim = q @ embn^T  (1-term bf16, bf16 keys out)
    k_mma_gemm<1,3><<<dim3(NQ / 128, NPAD / 128), 256, SM1>>>(
        qh, qh, embn, embn, nullptr, nullptr, sim, DIM, NPAD);

    // 6) exact top-50 set per query (on bf16 keys)
    k_topk<<<NQ, 256>>>(sim, idxp);

    // 7) distances -> weights -> weighted gene means
    k_predict<<<NQ, 256>>>(imgf, expr, emb, idxp, out);
}

// round 16
// speedup vs baseline: 1.1693x; 1.0182x over previous
#include <cuda_runtime.h>
#include <cuda_bf16.h>
#include <math.h>
#include <stdint.h>

#define NQ    2048
#define NREF  100000
#define GENES 3467
#define DIM   512
#define TOPK  50
#define LN_EPS 1e-5f

#define KPAD1 3520          // GENES padded to mult of 32
#define NPAD  100352        // NREF padded to mult of 128
#define RS    40            // smem row stride in bf16 (80B, conflict-free ldmatrix)

// ---------------- scratch (device globals; no allocation allowed) ----------
__device__ __nv_bfloat16 g_w1t_hi[(size_t)DIM * KPAD1];
__device__ __nv_bfloat16 g_w1t_lo[(size_t)DIM * KPAD1];
__device__ __nv_bfloat16 g_w2t_hi[(size_t)DIM * DIM];
__device__ __nv_bfloat16 g_w2t_lo[(size_t)DIM * DIM];
__device__ __nv_bfloat16 g_g_hi[(size_t)NPAD * DIM];
__device__ __nv_bfloat16 g_g_lo[(size_t)NPAD * DIM];
__device__ __nv_bfloat16 g_embn[(size_t)NPAD * DIM];
__device__ __nv_bfloat16 g_qhi[(size_t)NQ * DIM];
__device__ float g_proj[(size_t)NPAD * DIM];
__device__ float g_emb [(size_t)NPAD * DIM];
__device__ float g_rnorm[NREF];
__device__ __nv_bfloat16 g_sim [(size_t)NQ * NPAD];   // bf16 ranking keys
__device__ int   g_idx [NQ * TOPK];

// ---------------- PTX helpers (base compute_103 features only) --------------
__device__ __forceinline__ uint32_t smem_u32(const void* p) {
    uint32_t a;
    asm("{ .reg .u64 t; cvta.to.shared.u64 t, %1; cvt.u32.u64 %0, t; }" : "=r"(a) : "l"(p));
    return a;
}
__device__ __forceinline__ void cp16(uint32_t sa, const void* ga) {
    asm volatile("cp.async.cg.shared.global [%0], [%1], 16;" :: "r"(sa), "l"(ga));
}
#define CP_COMMIT() asm volatile("cp.async.commit_group;" ::: "memory")
#define CP_WAIT(n)  asm volatile("cp.async.wait_group %0;" :: "n"(n) : "memory")

__device__ __forceinline__ void ldm_x4(uint32_t* r, uint32_t addr) {
    asm volatile("ldmatrix.sync.aligned.m8n8.x4.shared.b16 {%0,%1,%2,%3}, [%4];"
        : "=r"(r[0]), "=r"(r[1]), "=r"(r[2]), "=r"(r[3]) : "r"(addr));
}
__device__ __forceinline__ void mma16816(float* d, const uint32_t* a, const uint32_t* b) {
    asm volatile(
        "mma.sync.aligned.m16n8k16.row.col.f32.bf16.bf16.f32 "
        "{%0,%1,%2,%3}, {%4,%5,%6,%7}, {%8,%9}, {%0,%1,%2,%3};"
        : "+f"(d[0]), "+f"(d[1]), "+f"(d[2]), "+f"(d[3])
        : "r"(a[0]), "r"(a[1]), "r"(a[2]), "r"(a[3]), "r"(b[0]), "r"(b[1]));
}

// ---------------- bf16 split helpers ----------------------------------------
__device__ __forceinline__ void split2(float x, __nv_bfloat16& h, __nv_bfloat16& l) {
    h = __float2bfloat16(x);
    l = __float2bfloat16(x - __bfloat162float(h));
}
__device__ __forceinline__ float gelu_exact(float x) {
    return 0.5f * x * (1.0f + erff(x * 0.70710678118654752f));
}

#define TILE_B (128 * RS * 2)   // 10240 bytes per tile

// ---- shared compute core: one BK=32 block, 3-term or 1-term -----------------
template<int TERMS>
__device__ __forceinline__ void compute_block(
    float acc[4][4][4], uint32_t sbase, int wm, int wn, int lane)
{
    const uint32_t saHI = sbase;
    const uint32_t saLO = sbase + TILE_B;
    const uint32_t sbHI = sbase + ((TERMS == 3) ? 2 : 1) * TILE_B;
    const uint32_t sbLO = sbase + 3 * TILE_B;
    #pragma unroll
    for (int ks = 0; ks < 2; ks++) {
        const int ko = ks * 16;
        const uint32_t aoff = (uint32_t)((wm + (lane & 15)) * RS + ko + (lane >> 4) * 8) * 2;
        const uint32_t boff = (uint32_t)((wn + ((lane >> 4) & 1) * 8 + (lane & 7)) * RS
                                         + ko + ((lane >> 3) & 1) * 8) * 2;
        uint32_t af[4][4], bf[2][4];
        #pragma unroll
        for (int i = 0; i < 4; i++) ldm_x4(af[i], saHI + aoff + i * 16 * RS * 2);
        #pragma unroll
        for (int p = 0; p < 2; p++) ldm_x4(bf[p], sbHI + boff + p * 16 * RS * 2);
        #pragma unroll
        for (int i = 0; i < 4; i++)
            #pragma unroll
            for (int j = 0; j < 4; j++)
                mma16816(acc[i][j], af[i], &bf[j >> 1][(j & 1) * 2]);
        if (TERMS == 3) {
            uint32_t bl[2][4];
            #pragma unroll
            for (int p = 0; p < 2; p++) ldm_x4(bl[p], sbLO + boff + p * 16 * RS * 2);
            #pragma unroll
            for (int i = 0; i < 4; i++)
                #pragma unroll
                for (int j = 0; j < 4; j++)
                    mma16816(acc[i][j], af[i], &bl[j >> 1][(j & 1) * 2]);
            #pragma unroll
            for (int i = 0; i < 4; i++) ldm_x4(af[i], saLO + aoff + i * 16 * RS * 2);
            #pragma unroll
            for (int i = 0; i < 4; i++)
                #pragma unroll
                for (int j = 0; j < 4; j++)
                    mma16816(acc[i][j], af[i], &bf[j >> 1][(j & 1) * 2]);
        }
    }
}

// ================= generic HMMA GEMM (R10-champion mainloop) =================
// C[M,N] = Ahl[M,K] @ Bhl[N,K]^T.  TERMS: 1 or 3.
// EPI: 1=f32+bias+resid, 3=bf16 raw.  Grid: x=row, y=col (proven).
template<int TERMS, int EPI>
__global__ __launch_bounds__(256) void k_mma_gemm(
    const __nv_bfloat16* __restrict__ Ahi, const __nv_bfloat16* __restrict__ Alo,
    const __nv_bfloat16* __restrict__ Bhi, const __nv_bfloat16* __restrict__ Blo,
    const float* __restrict__ bias, const float* __restrict__ resid,
    void* __restrict__ Cv, int K, int ldc)
{
    extern __shared__ char smem[];
    constexpr int NTILES = (TERMS == 3) ? 4 : 2;
    constexpr int STAGE  = TILE_B * NTILES;
    const uint32_t sb = smem_u32(smem);
    const int tid = threadIdx.x, wid = tid >> 5, lane = tid & 31;
    const int row0 = blockIdx.x * 128;
    const int col0 = blockIdx.y * 128;
    const int wm = (wid >> 2) * 64, wn = (wid & 3) * 32;

    float acc[4][4][4] = {};
    const int NKB = K / 32;

    auto load_stage = [&](int s, int kb) {
        const int kpos = kb * 32;
        const uint32_t sbase = sb + s * STAGE;
        #pragma unroll
        for (int i = 0; i < 2; i++) {
            const int idx = tid + i * 256;
            const int r = idx >> 2, c = idx & 3;
            const uint32_t so = r * (RS * 2) + c * 16;
            const size_t gA = (size_t)(row0 + r) * K + kpos + c * 8;
            const size_t gB = (size_t)(col0 + r) * K + kpos + c * 8;
            cp16(sbase + 0 * TILE_B + so, Ahi + gA);
            if (TERMS == 3) {
                cp16(sbase + 1 * TILE_B + so, Alo + gA);
                cp16(sbase + 2 * TILE_B + so, Bhi + gB);
                cp16(sbase + 3 * TILE_B + so, Blo + gB);
            } else {
                cp16(sbase + 1 * TILE_B + so, Bhi + gB);
            }
        }
    };

    load_stage(0, 0); CP_COMMIT();

    for (int kb = 0; kb < NKB; kb++) {
        const int s = kb & 1;
        if (kb + 1 < NKB) { load_stage(s ^ 1, kb + 1); CP_COMMIT(); CP_WAIT(1); }
        else              { CP_WAIT(0); }
        __syncthreads();
        compute_block<TERMS>(acc, sb + s * STAGE, wm, wn, lane);
        __syncthreads();
    }

    // ---- epilogue --------------------------------------------------------
    const int g  = lane >> 2;
    const int tg = (lane & 3) * 2;
    #pragma unroll
    for (int i = 0; i < 4; i++) {
        #pragma unroll
        for (int j = 0; j < 4; j++) {
            const int r = row0 + wm + i * 16 + g;
            const int c = col0 + wn + j * 8 + tg;
            float v0 = acc[i][j][0], v1 = acc[i][j][1];
            float v2 = acc[i][j][2], v3 = acc[i][j][3];
            if (EPI == 1) {
                const float b0 = bias[c], b1 = bias[c + 1];
                const float2 r0 = *(const float2*)&resid[(size_t)r * ldc + c];
                const float2 r1 = *(const float2*)&resid[(size_t)(r + 8) * ldc + c];
                v0 += b0 + r0.x; v1 += b1 + r0.y; v2 += b0 + r1.x; v3 += b1 + r1.y;
            }
            if (EPI == 3) {
                __nv_bfloat16* C = (__nv_bfloat16*)Cv;
                __nv_bfloat162 o0 = __floats2bfloat162_rn(v0, v1);
                __nv_bfloat162 o1 = __floats2bfloat162_rn(v2, v3);
                *(__nv_bfloat162*)&C[(size_t)r * ldc + c]       = o0;
                *(__nv_bfloat162*)&C[(size_t)(r + 8) * ldc + c] = o1;
            } else {
                float* C = (float*)Cv;
                float2 o0 = {v0, v1}, o1 = {v2, v3};
                *(float2*)&C[(size_t)r * ldc + c]       = o0;
                *(float2*)&C[(size_t)(r + 8) * ldc + c] = o1;
            }
        }
    }
}

// ========== GEMM1 fused: A f32->(hi,lo) in loader, gelu-split in epilogue ====
// proj = expr @ W1t^T + b1; also gh/gl = split(gelu(proj)) written directly.
__global__ __launch_bounds__(256, 2) void k_gemm1_fused(
    const float* __restrict__ expr,
    const __nv_bfloat16* __restrict__ Bhi, const __nv_bfloat16* __restrict__ Blo,
    const float* __restrict__ bias, float* __restrict__ C,
    __nv_bfloat16* __restrict__ gh, __nv_bfloat16* __restrict__ gl)
{
    extern __shared__ char smem[];
    constexpr int STAGE = TILE_B * 4;         // Ahi, Alo, Bhi, Blo
    const uint32_t sb = smem_u32(smem);
    const int tid = threadIdx.x, wid = tid >> 5, lane = tid & 31;
    const int row0 = blockIdx.x * 128;        // proven unswapped grid
    const int col0 = blockIdx.y * 128;
    const int wm = (wid >> 2) * 64, wn = (wid & 3) * 32;

    float acc[4][4][4] = {};
    const int NKB = KPAD1 / 32;               // 110

    auto ldgA = [&](int kb, float* v) {
        const int kpos = kb * 32;
        #pragma unroll
        for (int i = 0; i < 4; i++) {
            const int idx = tid + i * 256;
            const int r = idx >> 3, c4 = idx & 7;
            const int grow = row0 + r;
            const bool rowok = grow < NREF;
            const float* __restrict__ p = expr + (size_t)grow * GENES + kpos + c4 * 4;
            #pragma unroll
            for (int k = 0; k < 4; k++) {
                const int cg = kpos + c4 * 4 + k;
                v[i * 4 + k] = (rowok && cg < GENES) ? __ldg(p + k) : 0.0f;
            }
        }
    };
    auto stsA = [&](int s, const float* v) {
        #pragma unroll
        for (int i = 0; i < 4; i++) {
            const int idx = tid + i * 256;
            const int r = idx >> 3, c4 = idx & 7;
            __align__(8) __nv_bfloat16 h[4], l[4];
            #pragma unroll
            for (int k = 0; k < 4; k++) split2(v[i * 4 + k], h[k], l[k]);
            const uint32_t so = (uint32_t)(r * (RS * 2) + c4 * 8);
            const uint32_t off = s * STAGE;
            *(uint2*)(smem + off + 0 * TILE_B + so) = *(const uint2*)h;
            *(uint2*)(smem + off + 1 * TILE_B + so) = *(const uint2*)l;
        }
    };
    auto loadB = [&](int s, int kb) {
        const int kpos = kb * 32;
        const uint32_t sbase = sb + s * STAGE;
        #pragma unroll
        for (int i = 0; i < 2; i++) {
            const int idx = tid + i * 256;
            const int r = idx >> 2, c = idx & 3;
            const uint32_t so = r * (RS * 2) + c * 16;
            const size_t gB = (size_t)(col0 + r) * KPAD1 + kpos + c * 8;
            cp16(sbase + 2 * TILE_B + so, Bhi + gB);
            cp16(sbase + 3 * TILE_B + so, Blo + gB);
        }
    };

    float av[16];
    ldgA(0, av);
    loadB(0, 0); CP_COMMIT();
    stsA(0, av);
    ldgA(1, av);

    for (int kb = 0; kb < NKB; kb++) {
        const int s = kb & 1;
        if (kb + 1 < NKB) {
            loadB(s ^ 1, kb + 1);
            stsA(s ^ 1, av);
            CP_COMMIT();
            CP_WAIT(1);
            if (kb + 2 < NKB) ldgA(kb + 2, av);
        } else {
            CP_WAIT(0);
        }
        __syncthreads();
        compute_block<3>(acc, sb + s * STAGE, wm, wn, lane);
        __syncthreads();
    }

    // epilogue: proj = v + bias; gh/gl = split(gelu(proj))
    const int g  = lane >> 2;
    const int tg = (lane & 3) * 2;
    #pragma unroll
    for (int i = 0; i < 4; i++) {
        #pragma unroll
        for (int j = 0; j < 4; j++) {
            const int r = row0 + wm + i * 16 + g;
            const int c = col0 + wn + j * 8 + tg;
            const float b0 = bias[c], b1 = bias[c + 1];
            const float v0 = acc[i][j][0] + b0, v1 = acc[i][j][1] + b1;
            const float v2 = acc[i][j][2] + b0, v3 = acc[i][j][3] + b1;
            float2 o0 = {v0, v1}, o1 = {v2, v3};
            *(float2*)&C[(size_t)r * DIM + c]       = o0;
            *(float2*)&C[(size_t)(r + 8) * DIM + c] = o1;
            __nv_bfloat16 h0, l0, h1, l1, h2, l2, h3, l3;
            split2(gelu_exact(v0), h0, l0);
            split2(gelu_exact(v1), h1, l1);
            split2(gelu_exact(v2), h2, l2);
            split2(gelu_exact(v3), h3, l3);
            __nv_bfloat162 gh0; gh0.x = h0; gh0.y = h1;
            __nv_bfloat162 gh1; gh1.x = h2; gh1.y = h3;
            __nv_bfloat162 gl0; gl0.x = l0; gl0.y = l1;
            __nv_bfloat162 gl1; gl1.x = l2; gl1.y = l3;
            *(__nv_bfloat162*)&gh[(size_t)r * DIM + c]       = gh0;
            *(__nv_bfloat162*)&gh[(size_t)(r + 8) * DIM + c] = gh1;
            *(__nv_bfloat162*)&gl[(size_t)r * DIM + c]       = gl0;
            *(__nv_bfloat162*)&gl[(size_t)(r + 8) * DIM + c] = gl1;
        }
    }
}

// ================= conversion / split kernels ================================
// transpose+split W[K,N] -> out[N, KP] K-major
__global__ __launch_bounds__(256) void k_split_wt(const float* __restrict__ W,
    __nv_bfloat16* __restrict__ hi, __nv_bfloat16* __restrict__ lo, int Kreal, int KP)
{
    const long long idx = (long long)blockIdx.x * 256 + threadIdx.x;
    if (idx >= (long long)DIM * KP) return;
    const int n = (int)(idx / KP);
    const int k = (int)(idx % KP);
    const float v = (k < Kreal) ? W[(size_t)k * DIM + n] : 0.0f;
    __nv_bfloat16 h, l;
    split2(v, h, l);
    hi[idx] = h; lo[idx] = l;
}

__global__ __launch_bounds__(256) void k_split_q(const float* __restrict__ q,
    __nv_bfloat16* __restrict__ hi)
{
    const size_t idx = (size_t)blockIdx.x * 256 + threadIdx.x;
    if (idx >= (size_t)NQ * DIM) return;
    hi[idx] = __float2bfloat16(q[idx]);
}

// --------- LayerNorm (in place) + 1/||row|| + fused bf16 normalized copy ----
__global__ __launch_bounds__(128) void k_ln(
    float* __restrict__ h, const float* __restrict__ gamma,
    const float* __restrict__ beta, float* __restrict__ rnorm,
    __nv_bfloat16* __restrict__ embn)
{
    const int row = blockIdx.x;
    const int tid = threadIdx.x;
    if (row >= NREF) {                          // padded rows: zero embn only
        uint2 z = {0u, 0u};
        ((uint2*)(embn + (size_t)row * DIM))[tid] = z;
        return;
    }
    const int lane = tid & 31, warp = tid >> 5;
    __shared__ float red[4];

    float4 v = ((const float4*)(h + (size_t)row * DIM))[tid];
    float s = v.x + v.y + v.z + v.w;
    #pragma unroll
    for (int o = 16; o; o >>= 1) s += __shfl_xor_sync(0xFFFFFFFFu, s, o);
    if (lane == 0) red[warp] = s;
    __syncthreads();
    const float mu = (red[0] + red[1] + red[2] + red[3]) * (1.0f / DIM);
    __syncthreads();
    float dx = v.x - mu, dy = v.y - mu, dz = v.z - mu, dw = v.w - mu;
    float s2 = dx*dx + dy*dy + dz*dz + dw*dw;
    #pragma unroll
    for (int o = 16; o; o >>= 1) s2 += __shfl_xor_sync(0xFFFFFFFFu, s2, o);
    if (lane == 0) red[warp] = s2;
    __syncthreads();
    const float var = (red[0] + red[1] + red[2] + red[3]) * (1.0f / DIM);
    __syncthreads();
    const float rs = rsqrtf(var + LN_EPS);
    const int c = tid * 4;
    float4 y;
    y.x = dx * rs * gamma[c + 0] + beta[c + 0];
    y.y = dy * rs * gamma[c + 1] + beta[c + 1];
    y.z = dz * rs * gamma[c + 2] + beta[c + 2];
    y.w = dw * rs * gamma[c + 3] + beta[c + 3];
    float n2 = y.x*y.x + y.y*y.y + y.z*y.z + y.w*y.w;
    #pragma unroll
    for (int o = 16; o; o >>= 1) n2 += __shfl_xor_sync(0xFFFFFFFFu, n2, o);
    if (lane == 0) red[warp] = n2;
    __syncthreads();
    const float rn = rsqrtf(red[0] + red[1] + red[2] + red[3]);
    if (tid == 0) rnorm[row] = rn;
    ((float4*)(h + (size_t)row * DIM))[tid] = y;
    __nv_bfloat162 e0 = __floats2bfloat162_rn(y.x * rn, y.y * rn);
    __nv_bfloat162 e1 = __floats2bfloat162_rn(y.z * rn, y.w * rn);
    *(__nv_bfloat162*)(embn + (size_t)row * DIM + c)     = e0;
    *(__nv_bfloat162*)(embn + (size_t)row * DIM + c + 2) = e1;
}

// ---------------- top-50: 2 vectorized global passes + smem radix refine ----
__device__ __forceinline__ unsigned key16up(unsigned bits16) {
    const unsigned u = bits16 << 16;
    return (u & 0x80000000u) ? ~u : (u | 0x80000000u);   // monotone increasing
}

#define TKBINS   2048
#define CAND_CAP 4096
__global__ __launch_bounds__(256) void k_topk(
    const __nv_bfloat16* __restrict__ sim, int* __restrict__ out_idx)
{
    const int q = blockIdx.x;
    const int tid = threadIdx.x;
    const uint4* __restrict__ row8 = (const uint4*)(sim + (size_t)q * NPAD);
    const int N8 = NREF / 8;                       // 12500 exact

    __shared__ unsigned hist[TKBINS];
    __shared__ unsigned csum[256];
    __shared__ unsigned ckey[CAND_CAP];
    __shared__ int      cidx[CAND_CAP];
    __shared__ int sh_bin, cnt, sh_want, cnt2;
    __shared__ unsigned sh_prefix;

    // pass 1: 11-bit histogram, 8 keys per uint4 load
    for (int i = tid; i < TKBINS; i += 256) hist[i] = 0;
    __syncthreads();
    for (int j8 = tid; j8 < N8; j8 += 256) {
        const uint4 w = row8[j8];
        const unsigned ws[4] = {w.x, w.y, w.z, w.w};
        #pragma unroll
        for (int p = 0; p < 4; p++) {
            atomicAdd(&hist[key16up(ws[p] & 0xFFFFu) >> 21], 1u);
            atomicAdd(&hist[key16up(ws[p] >> 16) >> 21], 1u);
        }
    }
    __syncthreads();
    unsigned s = 0;
    #pragma unroll
    for (int b = 0; b < 8; b++) s += hist[tid * 8 + b];
    csum[tid] = s;
    __syncthreads();
    if (tid == 0) {
        unsigned cum = 0; int chunk = 255;
        for (; chunk > 0; chunk--) { if (cum + csum[chunk] >= TOPK) break; cum += csum[chunk]; }
        int b = chunk * 8 + 7;
        unsigned c2 = cum;
        for (; b > chunk * 8; b--) { if (c2 + hist[b] >= TOPK) break; c2 += hist[b]; }
        sh_bin = b;
        cnt = 0;
    }
    __syncthreads();
    const unsigned binT = (unsigned)sh_bin;

    // pass 2: collect candidate superset (vectorized)
    for (int j8 = tid; j8 < N8; j8 += 256) {
        const uint4 w = row8[j8];
        const unsigned ws[4] = {w.x, w.y, w.z, w.w};
        #pragma unroll
        for (int p = 0; p < 4; p++) {
            #pragma unroll
            for (int half = 0; half < 2; half++) {
                const unsigned k = key16up(half ? (ws[p] >> 16) : (ws[p] & 0xFFFFu));
                if ((k >> 21) >= binT) {
                    const int pos = atomicAdd(&cnt, 1);
                    if (pos < CAND_CAP) { ckey[pos] = k; cidx[pos] = j8 * 8 + p * 2 + half; }
                }
            }
        }
    }
    __syncthreads();
    const int L = min(cnt, CAND_CAP);

    unsigned prefix = 0; int want = TOPK;
    #pragma unroll 1
    for (int p = 3; p >= 0; --p) {
        __syncthreads();
        if (tid < 256) hist[tid] = 0;
        __syncthreads();
        for (int i = tid; i < L; i += 256) {
            const unsigned k = ckey[i];
            if (p == 3 || (k >> ((p + 1) * 8)) == prefix)
                atomicAdd(&hist[(k >> (p * 8)) & 255u], 1u);
        }
        __syncthreads();
        if (tid == 0) {
            unsigned cum = 0;
            for (int b = 255; b >= 0; --b) {
                cum += hist[b];
                if ((int)cum >= want) {
                    sh_want = want - (int)(cum - hist[b]);
                    sh_prefix = (prefix << 8) | (unsigned)b;
                    break;
                }
            }
            cnt2 = 0;
        }
        __syncthreads();
        prefix = sh_prefix;
        want = sh_want;
    }
    const unsigned T = prefix;

    for (int i = tid; i < L; i += 256) {
        if (ckey[i] > T) {
            const int p = atomicAdd(&cnt2, 1);
            if (p < TOPK) out_idx[q * TOPK + p] = cidx[i];
        }
    }
    __syncthreads();
    for (int i = tid; i < L; i += 256) {
        if (ckey[i] == T) {
            const int p = atomicAdd(&cnt2, 1);
            if (p < TOPK) out_idx[q * TOPK + p] = cidx[i];
        }
    }
}

// ---------------- distances + weights + weighted expression mean ------------
__global__ __launch_bounds__(256) void k_predict(
    const float* __restrict__ qf, const float* __restrict__ expr,
    const float* __restrict__ emb, const int* __restrict__ idx,
    float* __restrict__ out)
{
    const int q = blockIdx.x;
    const int tid = threadIdx.x;
    const int lane = tid & 31, warp = tid >> 5;

    __shared__ float sq[DIM];
    __shared__ int   sidx[TOPK];
    __shared__ float swt[TOPK];
    __shared__ float s_invw;

    for (int c = tid; c < DIM; c += 256) sq[c] = qf[(size_t)q * DIM + c];
    if (tid < TOPK) sidx[tid] = idx[q * TOPK + tid];
    __syncthreads();

    for (int k = warp; k < TOPK; k += 8) {
        const float* __restrict__ e = emb + (size_t)sidx[k] * DIM;
        float s = 0.0f;
        for (int c = lane; c < DIM; c += 32) {
            const float d = e[c] - sq[c];
            s = fmaf(d, d, s);
        }
        #pragma unroll
        for (int o = 16; o; o >>= 1) s += __shfl_xor_sync(0xFFFFFFFFu, s, o);
        if (lane == 0) swt[k] = s;
    }
    __syncthreads();

    if (tid == 0) {
        // anchor at min distance: pred is exactly invariant to anchor choice
        float a = swt[0];
        for (int k = 1; k < TOPK; k++) a = fminf(a, swt[k]);
        float sw = 0.0f;
        for (int k = 0; k < TOPK; k++) {
            const float w = expf(-(swt[k] - a + 1.0f));
            swt[k] = w;
            sw += w;
        }
        s_invw = 1.0f / sw;
    }
    __syncthreads();

    const float inv = s_invw;
    for (int g = tid; g < GENES; g += 256) {
        float acc = 0.0f;
        #pragma unroll 10
        for (int k = 0; k < TOPK; k++)
            acc = fmaf(swt[k], expr[(size_t)sidx[k] * GENES + g], acc);
        out[(size_t)q * GENES + g] = acc * inv;
    }
}

// ---------------- launch ----------------------------------------------------
extern "C" void kernel_launch(void* const* d_in, const int* in_sizes, int n_in,
                              void* d_out, int out_size)
{
    const float* imgf  = (const float*)d_in[0];
    const float* expr  = (const float*)d_in[1];
    const float* W1    = (const float*)d_in[2];
    const float* b1    = (const float*)d_in[3];
    const float* W2    = (const float*)d_in[4];
    const float* b2    = (const float*)d_in[5];
    const float* gamma = (const float*)d_in[6];
    const float* beta  = (const float*)d_in[7];
    float* out = (float*)d_out;

    __nv_bfloat16 *w1h, *w1l, *w2h, *w2l, *gh, *gl, *embn, *qh, *sim;
    float *proj, *emb, *rnorm;
    int *idxp;
    cudaGetSymbolAddress((void**)&w1h,  g_w1t_hi);
    cudaGetSymbolAddress((void**)&w1l,  g_w1t_lo);
    cudaGetSymbolAddress((void**)&w2h,  g_w2t_hi);
    cudaGetSymbolAddress((void**)&w2l,  g_w2t_lo);
    cudaGetSymbolAddress((void**)&gh,   g_g_hi);
    cudaGetSymbolAddress((void**)&gl,   g_g_lo);
    cudaGetSymbolAddress((void**)&embn, g_embn);
    cudaGetSymbolAddress((void**)&qh,   g_qhi);
    cudaGetSymbolAddress((void**)&sim,  g_sim);
    cudaGetSymbolAddress((void**)&proj, g_proj);
    cudaGetSymbolAddress((void**)&emb,  g_emb);
    cudaGetSymbolAddress((void**)&rnorm,g_rnorm);
    cudaGetSymbolAddress((void**)&idxp, g_idx);

    const int SM3 = 2 * 4 * TILE_B;   // 81920 B -> 2 CTAs/SM (proven)
    const int SM1 = 2 * 2 * TILE_B;   // 40960 B
    cudaFuncSetAttribute(k_gemm1_fused,   cudaFuncAttributeMaxDynamicSharedMemorySize, SM3);
    cudaFuncSetAttribute(k_mma_gemm<3,1>, cudaFuncAttributeMaxDynamicSharedMemorySize, SM3);
    cudaFuncSetAttribute(k_mma_gemm<1,3>, cudaFuncAttributeMaxDynamicSharedMemorySize, SM1);

    // 0) weight splits / q conversion (small)
    k_split_wt<<<(unsigned)(((size_t)DIM * KPAD1 + 255) / 256), 256>>>(W1, w1h, w1l, GENES, KPAD1);
    k_split_wt<<<(unsigned)(((size_t)DIM * DIM + 255) / 256), 256>>>(W2, w2h, w2l, DIM, DIM);
    k_split_q<<<(unsigned)(((size_t)NQ * DIM + 255) / 256), 256>>>(imgf, qh);

    // 1) proj = expr @ W1 + b1  (fused loader conversion + fused gelu-split epi)
    k_gemm1_fused<<<dim3(NPAD / 128, DIM / 128), 256, SM3>>>(
        expr, w1h, w1l, b1, proj, gh, gl);

    // 2) emb = gelu(proj) @ W2 + b2 + proj   (champion mainloop)
    k_mma_gemm<3,1><<<dim3(NPAD / 128, DIM / 128), 256, SM3>>>(
        gh, gl, w2h, w2l, b2, proj, emb, DIM, DIM);

    // 3) LayerNorm in place + 1/||row|| + fused bf16 normalized emb
    k_ln<<<NPAD, 128>>>(emb, gamma, beta, rnorm, embn);

    // 4) sim = q @ embn^T  (1-term bf16, bf16 keys out)
    k_mma_gemm<1,3><<<dim3(NQ / 128, NPAD / 128), 256, SM1>>>(
        qh, qh, embn, embn, nullptr, nullptr, sim, DIM, NPAD);

    // 5) exact top-50 set per query (vectorized bf16 key scan)
    k_topk<<<NQ, 256>>>(sim, idxp);

    // 6) distances -> weights -> weighted gene means
    k_predict<<<NQ, 256>>>(imgf, expr, emb, idxp, out);
}